// round 1
// baseline (speedup 1.0000x reference)
#include <cuda_runtime.h>
#include <cuda_bf16.h>
#include <stdint.h>

#define NB 4
#define NN 3600
#define NC 16
#define NW 128          /* padded adjacency words per row (113 used) */
#define NWU 113         /* ceil(3600/32) */
#define TR 120          /* rows per block in k_adj (30 tiles * 120 = 3600) */
#define K1_SMEM (5 * NN * 4)

// ---------------------------------------------------------------------------
// Scratch (device globals; no allocation)
// ---------------------------------------------------------------------------
__device__ unsigned int g_adj[NB][NN][NW];     // adjacency bitmask (7.4 MB)
__device__ float        g_adjcon[NB][NN][NC];  // per-box neighbor max of con

// ---------------------------------------------------------------------------
// K1: IoU adjacency. adj[i][j] = (iou >= 0.4) && i != j
// Bit-exact replication of the reference float op order (no FMA contraction).
// ---------------------------------------------------------------------------
__global__ __launch_bounds__(512) void k_adj(const float* __restrict__ boxes) {
    int b = blockIdx.y;
    extern __shared__ float sm[];
    float* sx1 = sm;
    float* sy1 = sm + NN;
    float* sx2 = sm + 2 * NN;
    float* sy2 = sm + 3 * NN;
    float* sar = sm + 4 * NN;

    const float4* bx = (const float4*)(boxes + (size_t)b * NN * 4);
    for (int i = threadIdx.x; i < NN; i += blockDim.x) {
        float4 v = bx[i];
        float x1 = __fsub_rn(v.x, __fmul_rn(v.z, 0.5f));
        float y1 = __fsub_rn(v.y, __fmul_rn(v.w, 0.5f));
        float x2 = __fadd_rn(x1, v.z);
        float y2 = __fadd_rn(y1, v.w);
        sx1[i] = x1; sy1[i] = y1; sx2[i] = x2; sy2[i] = y2;
        sar[i] = __fmul_rn(__fsub_rn(x2, x1), __fsub_rn(y2, y1));
    }
    __syncthreads();

    int lane = threadIdx.x & 31;
    int warp = threadIdx.x >> 5;
    int nw = blockDim.x >> 5;
    int r0 = blockIdx.x * TR;

    for (int t = warp; t < TR * NW; t += nw) {
        int i  = r0 + (t >> 7);       // row
        int wd = t & (NW - 1);        // word
        int j  = (wd << 5) + lane;
        bool ok = false;
        if (j < NN && j != i) {
            float rx1 = sx1[i], ry1 = sy1[i], rx2 = sx2[i], ry2 = sy2[i], ra = sar[i];
            float ltx = fmaxf(rx1, sx1[j]);
            float lty = fmaxf(ry1, sy1[j]);
            float rbx = fminf(rx2, sx2[j]);
            float rby = fminf(ry2, sy2[j]);
            float iw = fmaxf(__fsub_rn(rbx, ltx), 0.0f);
            float ih = fmaxf(__fsub_rn(rby, lty), 0.0f);
            float inter = __fmul_rn(iw, ih);
            float den = __fsub_rn(__fadd_rn(ra, sar[j]), inter);
            float iou = __fdiv_rn(inter, den);
            ok = (iou >= 0.4f);
        }
        unsigned m = __ballot_sync(0xffffffffu, ok);
        if (lane == 0) g_adj[b][i][wd] = m;
    }
}

// ---------------------------------------------------------------------------
// K2: adj_con[b][i][c] = max over neighbors j of con[b][j][c]  (0 if none)
// One warp per (b, i); all 16 classes at once.
// ---------------------------------------------------------------------------
__global__ __launch_bounds__(256) void k_adjcon(const float* __restrict__ con) {
    int g = (blockIdx.x * blockDim.x + threadIdx.x) >> 5;
    int lane = threadIdx.x & 31;
    if (g >= NB * NN) return;
    int b = g / NN;
    int i = g - b * NN;

    float4 m0 = make_float4(0.f, 0.f, 0.f, 0.f);
    float4 m1 = m0, m2 = m0, m3 = m0;
    const float4* crow = (const float4*)(con + (size_t)b * NN * NC);
    const unsigned* arow = g_adj[b][i];

    for (int wd = lane; wd < NWU; wd += 32) {
        unsigned m = arow[wd];
        while (m) {
            int bit = __ffs(m) - 1;
            m &= m - 1;
            int j = (wd << 5) + bit;
            const float4* cj = crow + (size_t)j * 4;
            float4 a = __ldg(cj + 0), bb = __ldg(cj + 1);
            float4 cc = __ldg(cj + 2), dd = __ldg(cj + 3);
            m0.x = fmaxf(m0.x, a.x);  m0.y = fmaxf(m0.y, a.y);
            m0.z = fmaxf(m0.z, a.z);  m0.w = fmaxf(m0.w, a.w);
            m1.x = fmaxf(m1.x, bb.x); m1.y = fmaxf(m1.y, bb.y);
            m1.z = fmaxf(m1.z, bb.z); m1.w = fmaxf(m1.w, bb.w);
            m2.x = fmaxf(m2.x, cc.x); m2.y = fmaxf(m2.y, cc.y);
            m2.z = fmaxf(m2.z, cc.z); m2.w = fmaxf(m2.w, cc.w);
            m3.x = fmaxf(m3.x, dd.x); m3.y = fmaxf(m3.y, dd.y);
            m3.z = fmaxf(m3.z, dd.z); m3.w = fmaxf(m3.w, dd.w);
        }
    }
#define WRED(f) { for (int o = 16; o > 0; o >>= 1) f = fmaxf(f, __shfl_xor_sync(0xffffffffu, f, o)); }
    WRED(m0.x) WRED(m0.y) WRED(m0.z) WRED(m0.w)
    WRED(m1.x) WRED(m1.y) WRED(m1.z) WRED(m1.w)
    WRED(m2.x) WRED(m2.y) WRED(m2.z) WRED(m2.w)
    WRED(m3.x) WRED(m3.y) WRED(m3.z) WRED(m3.w)
#undef WRED
    if (lane == 0) {
        float4* dst = (float4*)&g_adjcon[b][i][0];
        dst[0] = m0; dst[1] = m1; dst[2] = m2; dst[3] = m3;
    }
}

// ---------------------------------------------------------------------------
// K3: per-(image, class) NMS. One block per (b, c).
// ---------------------------------------------------------------------------
__global__ __launch_bounds__(256) void k_nms(
    const float* __restrict__ pro, const float* __restrict__ con,
    const float* __restrict__ boxes, const float* __restrict__ scales,
    const float* __restrict__ conf, float* __restrict__ out, int maskMode)
{
    __shared__ unsigned long long skey[4096];   // 32 KB
    __shared__ int ssorted[NN];                 // 14.4 KB
    __shared__ unsigned int svalid[NW];         // 512 B
    __shared__ int scount;
    __shared__ int sS;

    int c = blockIdx.x, b = blockIdx.y;
    int tid = threadIdx.x;
    int lane = tid & 31;

    if (tid < NW) svalid[tid] = 0u;
    if (tid == 0) { scount = 0; sS = 0; }
    __syncthreads();

    // -------- candidate build: valid0 = pro>=conf && pro>=con && pro>=adj_con
    float confc = conf[c];
    for (int i = tid; i < NN; i += blockDim.x) {
        size_t base = ((size_t)b * NN + i) * NC + c;
        float p  = pro[base];
        float cn = con[base];
        float ac = g_adjcon[b][i][c];
        if (p >= confc && p >= cn && p >= ac) {
            atomicOr(&svalid[i >> 5], 1u << (i & 31));
            int pos = atomicAdd(&scount, 1);
            skey[pos] = ((unsigned long long)__float_as_uint(p) << 32)
                      | (unsigned long long)(0xFFFFFFFFu - (unsigned)i);
        }
    }
    __syncthreads();
    int K = scount;
    int Kp = 1;
    while (Kp < K) Kp <<= 1;

    for (int t = K + tid; t < Kp; t += blockDim.x) skey[t] = 0ULL;
    __syncthreads();

    // -------- bitonic sort descending (score desc, idx asc — matches stable argsort)
    for (int k2 = 2; k2 <= Kp; k2 <<= 1) {
        for (int j = k2 >> 1; j > 0; j >>= 1) {
            for (int i = tid; i < Kp; i += blockDim.x) {
                int ixj = i ^ j;
                if (ixj > i) {
                    unsigned long long a = skey[i], bb2 = skey[ixj];
                    bool up = ((i & k2) == 0);
                    if (up ? (a < bb2) : (a > bb2)) { skey[i] = bb2; skey[ixj] = a; }
                }
            }
            __syncthreads();
        }
    }

    // -------- greedy suppression + survivor extraction (warp 0)
    if (tid < 32) {
        const uint4* adjB = (const uint4*)&g_adj[b][0][0];  // row i -> adjB + i*32
        uint4 v = ((uint4*)svalid)[lane];
        uint4 z = make_uint4(0u, 0u, 0u, 0u);
        uint4 pf0 = z, pf1 = z, pf2 = z, pf3 = z;
#define IDXAT(k) ((int)(0xFFFFFFFFu - (unsigned)skey[(k)]))
        if (K > 0) pf0 = adjB[(size_t)IDXAT(0) * 32 + lane];
        if (K > 1) pf1 = adjB[(size_t)IDXAT(1) * 32 + lane];
        if (K > 2) pf2 = adjB[(size_t)IDXAT(2) * 32 + lane];
        if (K > 3) pf3 = adjB[(size_t)IDXAT(3) * 32 + lane];
#define GSTEP(kk, pf)                                                         \
        if ((kk) < K) {                                                       \
            int idx = IDXAT(kk);                                              \
            int wdq = idx >> 5;                                               \
            unsigned vw;                                                      \
            switch (wdq & 3) {                                                \
                case 0:  vw = __shfl_sync(0xffffffffu, v.x, wdq >> 2); break; \
                case 1:  vw = __shfl_sync(0xffffffffu, v.y, wdq >> 2); break; \
                case 2:  vw = __shfl_sync(0xffffffffu, v.z, wdq >> 2); break; \
                default: vw = __shfl_sync(0xffffffffu, v.w, wdq >> 2); break; \
            }                                                                 \
            if ((vw >> (idx & 31)) & 1u) {                                    \
                v.x &= ~pf.x; v.y &= ~pf.y; v.z &= ~pf.z; v.w &= ~pf.w;       \
            }                                                                 \
            if ((kk) + 4 < K) pf = adjB[(size_t)IDXAT((kk) + 4) * 32 + lane]; \
        }
        for (int k = 0; k < K; k += 4) {
            GSTEP(k,     pf0)
            GSTEP(k + 1, pf1)
            GSTEP(k + 2, pf2)
            GSTEP(k + 3, pf3)
        }
#undef GSTEP
        ((uint4*)svalid)[lane] = v;
        __syncwarp();

        int base = 0;
        for (int k0 = 0; k0 < K; k0 += 32) {
            int kk = k0 + lane;
            bool sv = false;
            int idx = 0;
            if (kk < K) {
                idx = IDXAT(kk);
                sv = (svalid[idx >> 5] >> (idx & 31)) & 1u;
            }
            unsigned mm = __ballot_sync(0xffffffffu, sv);
            if (sv) ssorted[base + __popc(mm & ((1u << lane) - 1u))] = idx;
            base += __popc(mm);
        }
        if (lane == 0) sS = base;
#undef IDXAT
    }
    __syncthreads();

    // -------- write outputs: survivors in slots [0,S), zeros after
    int S = sS;
    float scl = scales[b];
    float* ob = out + ((size_t)(b * NC + c)) * NN * 5;
    for (int t = tid; t < NN; t += blockDim.x) {
        float r0 = 0.f, r1 = 0.f, r2 = 0.f, r3 = 0.f, r4 = 0.f;
        if (t < S) {
            int idx = ssorted[t];
            float4 bxv = __ldg(&((const float4*)boxes)[(size_t)b * NN + idx]);
            float bcx = __fmul_rn(bxv.x, scl);
            float bcy = __fmul_rn(bxv.y, scl);
            float hw = __fmul_rn(0.5f, __fmul_rn(bxv.z, scl));
            float hh = __fmul_rn(0.5f, __fmul_rn(bxv.w, scl));
            r0 = __fsub_rn(bcx, hw);
            r1 = __fsub_rn(bcy, hh);
            r2 = __fadd_rn(bcx, hw);
            r3 = __fadd_rn(bcy, hh);
            r4 = pro[((size_t)b * NN + idx) * NC + c];
        }
        float* p5 = ob + (size_t)t * 5;
        p5[0] = r0; p5[1] = r1; p5[2] = r2; p5[3] = r3; p5[4] = r4;
    }
    if (maskMode == 1) {
        float* mb = out + (size_t)NB * NC * NN * 5 + (size_t)(b * NC + c) * NN;
        for (int t = tid; t < NN; t += blockDim.x) mb[t] = (t < S) ? 1.0f : 0.0f;
    } else if (maskMode == 2) {
        unsigned char* mb = (unsigned char*)(out + (size_t)NB * NC * NN * 5)
                          + (size_t)(b * NC + c) * NN;
        for (int t = tid; t < NN; t += blockDim.x) mb[t] = (t < S) ? 1 : 0;
    }
}

// ---------------------------------------------------------------------------
// Launch
// ---------------------------------------------------------------------------
extern "C" void kernel_launch(void* const* d_in, const int* in_sizes, int n_in,
                              void* d_out, int out_size) {
    const float* pro    = (const float*)d_in[0];  // (B,N,C)
    const float* con    = (const float*)d_in[1];  // (B,N,C)
    const float* boxes  = (const float*)d_in[2];  // (B,N,4)
    const float* scales = (const float*)d_in[3];  // (B,)
    const float* conf   = (const float*)d_in[4];  // (C,)
    float* out = (float*)d_out;

    cudaFuncSetAttribute(k_adj, cudaFuncAttributeMaxDynamicSharedMemorySize, K1_SMEM);

    long long T5 = (long long)NB * NC * NN * 5;   // 1,152,000
    long long TM = (long long)NB * NC * NN;       //   230,400
    int maskMode = 0;
    if ((long long)out_size >= T5 + TM) maskMode = 1;       // mask as float
    else if ((long long)out_size > T5)  maskMode = 2;       // mask as bytes

    k_adj<<<dim3(NN / TR, NB), 512, K1_SMEM>>>(boxes);
    k_adjcon<<<(NB * NN * 32 + 255) / 256, 256>>>(con);
    k_nms<<<dim3(NC, NB), 256>>>(pro, con, boxes, scales, conf, out, maskMode);
}

// round 2
// speedup vs baseline: 1.6352x; 1.6352x over previous
#include <cuda_runtime.h>
#include <cuda_bf16.h>
#include <stdint.h>

#define NB 4
#define NN 3600
#define NC 16
#define NW 128          /* padded adjacency words per row (113 used) */
#define NWU 113         /* ceil(3600/32) */
#define NPAD 3616       /* boxes padded to multiple of 32 */
#define TRR 48          /* rows per block in k_adj */
#define RPW 6           /* rows per warp (8 warps * 6 = 48) */
#define K1_SMEM (NPAD * 16)

// ---------------------------------------------------------------------------
// Scratch (device globals; no allocation)
// ---------------------------------------------------------------------------
__device__ unsigned int g_adj[NB][NN][NW];     // adjacency bitmask (7.4 MB)
__device__ float        g_adjcon[NB][NN][NC];  // per-box neighbor max of con

// ---------------------------------------------------------------------------
// K1: IoU adjacency, register-tiled. adj[i][j] = (iou >= 0.4) && i != j
// Bit-exact replication of the reference float op order (no FMA contraction).
// Each warp holds RPW rows in registers; per column word: 1 LDS.128 + 6 IoUs.
// ---------------------------------------------------------------------------
__global__ __launch_bounds__(256, 3) void k_adj(const float* __restrict__ boxes) {
    int b = blockIdx.y;
    extern __shared__ float4 sb[];   // NPAD boxes as (x1, y1, x2, y2)

    const float4* bx = (const float4*)(boxes + (size_t)b * NN * 4);
    for (int i = threadIdx.x; i < NPAD; i += 256) {
        float4 r;
        if (i < NN) {
            float4 v = bx[i];
            float x1 = __fsub_rn(v.x, __fmul_rn(v.z, 0.5f));
            float y1 = __fsub_rn(v.y, __fmul_rn(v.w, 0.5f));
            r = make_float4(x1, y1, __fadd_rn(x1, v.z), __fadd_rn(y1, v.w));
        } else {
            // pad: inter = 0, area = +inf  ->  iou = 0 / inf = 0 -> false
            r = make_float4(3e30f, 3e30f, -3e30f, -3e30f);
        }
        sb[i] = r;
    }
    __syncthreads();

    int warp = threadIdx.x >> 5, lane = threadIdx.x & 31;
    int r0 = blockIdx.x * TRR + warp * RPW;

    float rx1[RPW], ry1[RPW], rx2[RPW], ry2[RPW], ra[RPW];
#pragma unroll
    for (int r = 0; r < RPW; r++) {
        float4 v = sb[r0 + r];
        rx1[r] = v.x; ry1[r] = v.y; rx2[r] = v.z; ry2[r] = v.w;
        ra[r] = __fmul_rn(__fsub_rn(v.z, v.x), __fsub_rn(v.w, v.y));
    }

    unsigned* adjb = &g_adj[b][0][0];
    for (int wd = 0; wd < NWU; wd++) {
        float4 v = sb[(wd << 5) + lane];
        float aj = __fmul_rn(__fsub_rn(v.z, v.x), __fsub_rn(v.w, v.y));
#pragma unroll
        for (int r = 0; r < RPW; r++) {
            int i = r0 + r;
            float ltx = fmaxf(rx1[r], v.x);
            float lty = fmaxf(ry1[r], v.y);
            float rbx = fminf(rx2[r], v.z);
            float rby = fminf(ry2[r], v.w);
            float iw = fmaxf(__fsub_rn(rbx, ltx), 0.0f);
            float ih = fmaxf(__fsub_rn(rby, lty), 0.0f);
            float inter = __fmul_rn(iw, ih);
            float den = __fsub_rn(__fadd_rn(ra[r], aj), inter);
            bool ok = (__fdiv_rn(inter, den) >= 0.4f);
            unsigned m = __ballot_sync(0xffffffffu, ok);
            if (lane == 0) {
                if (wd == (i >> 5)) m &= ~(1u << (i & 31));  // ~eye
                adjb[(size_t)i * NW + wd] = m;
            }
        }
    }

    // zero padded words 113..127 so K2/K3 can vector-scan NW words safely
    for (int t = threadIdx.x; t < TRR * (NW - NWU); t += 256) {
        int r = t / (NW - NWU), w = t - r * (NW - NWU);
        adjb[(size_t)(blockIdx.x * TRR + r) * NW + NWU + w] = 0u;
    }
}

// ---------------------------------------------------------------------------
// K2: adj_con[b][i][c] = max over neighbors j of con[b][j][c]  (0 if none)
// One warp per (b, i); all 16 classes at once; uint4 word scan.
// ---------------------------------------------------------------------------
__global__ __launch_bounds__(256) void k_adjcon(const float* __restrict__ con) {
    int g = (blockIdx.x * blockDim.x + threadIdx.x) >> 5;
    int lane = threadIdx.x & 31;
    if (g >= NB * NN) return;
    int b = g / NN;
    int i = g - b * NN;

    float4 m0 = make_float4(0.f, 0.f, 0.f, 0.f);
    float4 m1 = m0, m2 = m0, m3 = m0;
    const float4* crow = (const float4*)(con + (size_t)b * NN * NC);
    uint4 wv = ((const uint4*)&g_adj[b][i][0])[lane];   // words 4*lane..4*lane+3

#pragma unroll
    for (int s = 0; s < 4; s++) {
        unsigned m = (s == 0) ? wv.x : (s == 1) ? wv.y : (s == 2) ? wv.z : wv.w;
        int jbase = (lane << 7) + (s << 5);
        while (m) {
            int bit = __ffs(m) - 1;
            m &= m - 1;
            int j = jbase + bit;
            const float4* cj = crow + (size_t)j * 4;
            float4 a = __ldg(cj + 0), bb = __ldg(cj + 1);
            float4 cc = __ldg(cj + 2), dd = __ldg(cj + 3);
            m0.x = fmaxf(m0.x, a.x);  m0.y = fmaxf(m0.y, a.y);
            m0.z = fmaxf(m0.z, a.z);  m0.w = fmaxf(m0.w, a.w);
            m1.x = fmaxf(m1.x, bb.x); m1.y = fmaxf(m1.y, bb.y);
            m1.z = fmaxf(m1.z, bb.z); m1.w = fmaxf(m1.w, bb.w);
            m2.x = fmaxf(m2.x, cc.x); m2.y = fmaxf(m2.y, cc.y);
            m2.z = fmaxf(m2.z, cc.z); m2.w = fmaxf(m2.w, cc.w);
            m3.x = fmaxf(m3.x, dd.x); m3.y = fmaxf(m3.y, dd.y);
            m3.z = fmaxf(m3.z, dd.z); m3.w = fmaxf(m3.w, dd.w);
        }
    }
#define WRED(f) { for (int o = 16; o > 0; o >>= 1) f = fmaxf(f, __shfl_xor_sync(0xffffffffu, f, o)); }
    WRED(m0.x) WRED(m0.y) WRED(m0.z) WRED(m0.w)
    WRED(m1.x) WRED(m1.y) WRED(m1.z) WRED(m1.w)
    WRED(m2.x) WRED(m2.y) WRED(m2.z) WRED(m2.w)
    WRED(m3.x) WRED(m3.y) WRED(m3.z) WRED(m3.w)
#undef WRED
    if (lane == 0) {
        float4* dst = (float4*)&g_adjcon[b][i][0];
        dst[0] = m0; dst[1] = m1; dst[2] = m2; dst[3] = m3;
    }
}

// ---------------------------------------------------------------------------
// K3: per-(image, class) NMS. One block per (b, c).
// ---------------------------------------------------------------------------
__global__ __launch_bounds__(256) void k_nms(
    const float* __restrict__ pro, const float* __restrict__ con,
    const float* __restrict__ boxes, const float* __restrict__ scales,
    const float* __restrict__ conf, float* __restrict__ out, int maskMode)
{
    __shared__ unsigned long long skey[4096];   // 32 KB
    __shared__ int ssorted[NN];                 // 14.4 KB
    __shared__ unsigned int svalid[NW];         // 512 B
    __shared__ int scount;
    __shared__ int sS;

    int c = blockIdx.x, b = blockIdx.y;
    int tid = threadIdx.x;
    int lane = tid & 31;

    if (tid < NW) svalid[tid] = 0u;
    if (tid == 0) { scount = 0; sS = 0; }
    __syncthreads();

    // -------- candidate build: valid0 = pro>=conf && pro>=con && pro>=adj_con
    float confc = conf[c];
    for (int i = tid; i < NN; i += blockDim.x) {
        size_t base = ((size_t)b * NN + i) * NC + c;
        float p  = pro[base];
        float cn = con[base];
        float ac = g_adjcon[b][i][c];
        if (p >= confc && p >= cn && p >= ac) {
            atomicOr(&svalid[i >> 5], 1u << (i & 31));
            int pos = atomicAdd(&scount, 1);
            skey[pos] = ((unsigned long long)__float_as_uint(p) << 32)
                      | (unsigned long long)(0xFFFFFFFFu - (unsigned)i);
        }
    }
    __syncthreads();
    int K = scount;
    int Kp = 1;
    while (Kp < K) Kp <<= 1;

    for (int t = K + tid; t < Kp; t += blockDim.x) skey[t] = 0ULL;
    __syncthreads();

    // -------- bitonic sort descending (score desc, idx asc — matches stable argsort)
    for (int k2 = 2; k2 <= Kp; k2 <<= 1) {
        for (int j = k2 >> 1; j > 0; j >>= 1) {
            for (int i = tid; i < Kp; i += blockDim.x) {
                int ixj = i ^ j;
                if (ixj > i) {
                    unsigned long long a = skey[i], bb2 = skey[ixj];
                    bool up = ((i & k2) == 0);
                    if (up ? (a < bb2) : (a > bb2)) { skey[i] = bb2; skey[ixj] = a; }
                }
            }
            __syncthreads();
        }
    }

    // -------- greedy suppression + survivor extraction (warp 0)
    if (tid < 32) {
        const uint4* adjB = (const uint4*)&g_adj[b][0][0];  // row i -> adjB + i*32
        uint4 v = ((uint4*)svalid)[lane];
        uint4 z = make_uint4(0u, 0u, 0u, 0u);
        uint4 pf0 = z, pf1 = z, pf2 = z, pf3 = z;
#define IDXAT(k) ((int)(0xFFFFFFFFu - (unsigned)skey[(k)]))
        if (K > 0) pf0 = adjB[(size_t)IDXAT(0) * 32 + lane];
        if (K > 1) pf1 = adjB[(size_t)IDXAT(1) * 32 + lane];
        if (K > 2) pf2 = adjB[(size_t)IDXAT(2) * 32 + lane];
        if (K > 3) pf3 = adjB[(size_t)IDXAT(3) * 32 + lane];
#define GSTEP(kk, pf)                                                         \
        if ((kk) < K) {                                                       \
            int idx = IDXAT(kk);                                              \
            int wdq = idx >> 5;                                               \
            unsigned vw;                                                      \
            switch (wdq & 3) {                                                \
                case 0:  vw = __shfl_sync(0xffffffffu, v.x, wdq >> 2); break; \
                case 1:  vw = __shfl_sync(0xffffffffu, v.y, wdq >> 2); break; \
                case 2:  vw = __shfl_sync(0xffffffffu, v.z, wdq >> 2); break; \
                default: vw = __shfl_sync(0xffffffffu, v.w, wdq >> 2); break; \
            }                                                                 \
            if ((vw >> (idx & 31)) & 1u) {                                    \
                v.x &= ~pf.x; v.y &= ~pf.y; v.z &= ~pf.z; v.w &= ~pf.w;       \
            }                                                                 \
            if ((kk) + 4 < K) pf = adjB[(size_t)IDXAT((kk) + 4) * 32 + lane]; \
        }
        for (int k = 0; k < K; k += 4) {
            GSTEP(k,     pf0)
            GSTEP(k + 1, pf1)
            GSTEP(k + 2, pf2)
            GSTEP(k + 3, pf3)
        }
#undef GSTEP
        ((uint4*)svalid)[lane] = v;
        __syncwarp();

        int base = 0;
        for (int k0 = 0; k0 < K; k0 += 32) {
            int kk = k0 + lane;
            bool sv = false;
            int idx = 0;
            if (kk < K) {
                idx = IDXAT(kk);
                sv = (svalid[idx >> 5] >> (idx & 31)) & 1u;
            }
            unsigned mm = __ballot_sync(0xffffffffu, sv);
            if (sv) ssorted[base + __popc(mm & ((1u << lane) - 1u))] = idx;
            base += __popc(mm);
        }
        if (lane == 0) sS = base;
#undef IDXAT
    }
    __syncthreads();

    // -------- write outputs: survivors in slots [0,S), zeros after
    int S = sS;
    float scl = scales[b];
    float* ob = out + ((size_t)(b * NC + c)) * NN * 5;
    for (int t = tid; t < NN; t += blockDim.x) {
        float r0 = 0.f, r1 = 0.f, r2 = 0.f, r3 = 0.f, r4 = 0.f;
        if (t < S) {
            int idx = ssorted[t];
            float4 bxv = __ldg(&((const float4*)boxes)[(size_t)b * NN + idx]);
            float bcx = __fmul_rn(bxv.x, scl);
            float bcy = __fmul_rn(bxv.y, scl);
            float hw = __fmul_rn(0.5f, __fmul_rn(bxv.z, scl));
            float hh = __fmul_rn(0.5f, __fmul_rn(bxv.w, scl));
            r0 = __fsub_rn(bcx, hw);
            r1 = __fsub_rn(bcy, hh);
            r2 = __fadd_rn(bcx, hw);
            r3 = __fadd_rn(bcy, hh);
            r4 = pro[((size_t)b * NN + idx) * NC + c];
        }
        float* p5 = ob + (size_t)t * 5;
        p5[0] = r0; p5[1] = r1; p5[2] = r2; p5[3] = r3; p5[4] = r4;
    }
    if (maskMode == 1) {
        float* mb = out + (size_t)NB * NC * NN * 5 + (size_t)(b * NC + c) * NN;
        for (int t = tid; t < NN; t += blockDim.x) mb[t] = (t < S) ? 1.0f : 0.0f;
    } else if (maskMode == 2) {
        unsigned char* mb = (unsigned char*)(out + (size_t)NB * NC * NN * 5)
                          + (size_t)(b * NC + c) * NN;
        for (int t = tid; t < NN; t += blockDim.x) mb[t] = (t < S) ? 1 : 0;
    }
}

// ---------------------------------------------------------------------------
// Launch
// ---------------------------------------------------------------------------
extern "C" void kernel_launch(void* const* d_in, const int* in_sizes, int n_in,
                              void* d_out, int out_size) {
    const float* pro    = (const float*)d_in[0];  // (B,N,C)
    const float* con    = (const float*)d_in[1];  // (B,N,C)
    const float* boxes  = (const float*)d_in[2];  // (B,N,4)
    const float* scales = (const float*)d_in[3];  // (B,)
    const float* conf   = (const float*)d_in[4];  // (C,)
    float* out = (float*)d_out;

    cudaFuncSetAttribute(k_adj, cudaFuncAttributeMaxDynamicSharedMemorySize, K1_SMEM);

    long long T5 = (long long)NB * NC * NN * 5;   // 1,152,000
    long long TM = (long long)NB * NC * NN;       //   230,400
    int maskMode = 0;
    if ((long long)out_size >= T5 + TM) maskMode = 1;       // mask as float
    else if ((long long)out_size > T5)  maskMode = 2;       // mask as bytes

    k_adj<<<dim3(NN / TRR, NB), 256, K1_SMEM>>>(boxes);
    k_adjcon<<<(NB * NN * 32 + 255) / 256, 256>>>(con);
    k_nms<<<dim3(NC, NB), 256>>>(pro, con, boxes, scales, conf, out, maskMode);
}

// round 3
// speedup vs baseline: 2.2602x; 1.3823x over previous
#include <cuda_runtime.h>
#include <cuda_bf16.h>
#include <stdint.h>

#define NB 4
#define NN 3600
#define NC 16
#define NW 128          /* padded adjacency words per row (113 used) */
#define NWU 113         /* ceil(3600/32) */
#define NPAD 3616       /* boxes padded to multiple of 32 */
#define TRR 30          /* rows per block in k_adj */
#define RPW 3           /* rows per warp (10 warps * 3 = 30) */
#define K1_SMEM (NPAD * 16)

// ---------------------------------------------------------------------------
// Scratch (device globals; no allocation)
// ---------------------------------------------------------------------------
__device__ unsigned int g_adj[NB][NN][NW];     // adjacency bitmask (7.4 MB)
__device__ float        g_adjcon[NB][NN][NC];  // per-box neighbor max of con

// ---------------------------------------------------------------------------
// K1: IoU adjacency, register-tiled. adj[i][j] = (iou >= 0.4) && i != j
// Division avoided via a rigorous two-sided product screen; only boundary /
// degenerate lanes fall back to the exact __fdiv_rn (bit-identical result).
// ---------------------------------------------------------------------------
__global__ __launch_bounds__(320, 3) void k_adj(const float* __restrict__ boxes) {
    int b = blockIdx.y;
    extern __shared__ float4 sb[];   // NPAD boxes as (x1, y1, x2, y2)

    const float4* bx = (const float4*)(boxes + (size_t)b * NN * 4);
    for (int i = threadIdx.x; i < NPAD; i += 320) {
        float4 r;
        if (i < NN) {
            float4 v = bx[i];
            float x1 = __fsub_rn(v.x, __fmul_rn(v.z, 0.5f));
            float y1 = __fsub_rn(v.y, __fmul_rn(v.w, 0.5f));
            r = make_float4(x1, y1, __fadd_rn(x1, v.z), __fadd_rn(y1, v.w));
        } else {
            // pad: inter = 0, area = +inf  ->  iou = 0 -> false
            r = make_float4(3e30f, 3e30f, -3e30f, -3e30f);
        }
        sb[i] = r;
    }
    __syncthreads();

    int warp = threadIdx.x >> 5, lane = threadIdx.x & 31;
    int r0 = blockIdx.x * TRR + warp * RPW;

    float rx1[RPW], ry1[RPW], rx2[RPW], ry2[RPW], ra[RPW];
    int wi[RPW]; unsigned em[RPW];
#pragma unroll
    for (int r = 0; r < RPW; r++) {
        float4 v = sb[r0 + r];
        rx1[r] = v.x; ry1[r] = v.y; rx2[r] = v.z; ry2[r] = v.w;
        ra[r] = __fmul_rn(__fsub_rn(v.z, v.x), __fsub_rn(v.w, v.y));
        wi[r] = (r0 + r) >> 5;
        em[r] = ~(1u << ((r0 + r) & 31));
    }

    unsigned* adjb = &g_adj[b][0][0];
    for (int wd = 0; wd < NWU; wd++) {
        float4 v = sb[(wd << 5) + lane];
        float aj = __fmul_rn(__fsub_rn(v.z, v.x), __fsub_rn(v.w, v.y));
#pragma unroll
        for (int r = 0; r < RPW; r++) {
            float ltx = fmaxf(rx1[r], v.x);
            float lty = fmaxf(ry1[r], v.y);
            float rbx = fminf(rx2[r], v.z);
            float rby = fminf(ry2[r], v.w);
            float iw = fmaxf(__fsub_rn(rbx, ltx), 0.0f);
            float ih = fmaxf(__fsub_rn(rby, lty), 0.0f);
            float inter = __fmul_rn(iw, ih);
            float den = __fsub_rn(__fadd_rn(ra[r], aj), inter);
            // screen: decide almost all lanes with 2 products
            float ph = __fmul_rn(den, 0.4000002f);
            float pl = __fmul_rn(den, 0.3999998f);
            bool ok  = (inter > ph);
            bool amb = (!ok) && !(inter < pl);   // boundary band / NaN / 0/0
            if (__any_sync(0xffffffffu, amb)) {
                if (amb) ok = (__fdiv_rn(inter, den) >= 0.4f);
            }
            unsigned m = __ballot_sync(0xffffffffu, ok);
            if (lane == 0) {
                if (wd == wi[r]) m &= em[r];     // ~eye
                adjb[(size_t)(r0 + r) * NW + wd] = m;
            }
        }
    }

    // zero padded words 113..127 so K2/K3 can vector-scan NW words safely
    for (int t = threadIdx.x; t < TRR * (NW - NWU); t += 320) {
        int r = t / (NW - NWU), w = t - r * (NW - NWU);
        adjb[(size_t)(blockIdx.x * TRR + r) * NW + NWU + w] = 0u;
    }
}

// ---------------------------------------------------------------------------
// K2: adj_con[b][i][c] = max over neighbors j of con[b][j][c]  (0 if none)
// One warp per (b, i); all 16 classes at once; uint4 word scan.
// ---------------------------------------------------------------------------
__global__ __launch_bounds__(256) void k_adjcon(const float* __restrict__ con) {
    int g = (blockIdx.x * blockDim.x + threadIdx.x) >> 5;
    int lane = threadIdx.x & 31;
    if (g >= NB * NN) return;
    int b = g / NN;
    int i = g - b * NN;

    float4 m0 = make_float4(0.f, 0.f, 0.f, 0.f);
    float4 m1 = m0, m2 = m0, m3 = m0;
    const float4* crow = (const float4*)(con + (size_t)b * NN * NC);
    uint4 wv = ((const uint4*)&g_adj[b][i][0])[lane];   // words 4*lane..4*lane+3

#pragma unroll
    for (int s = 0; s < 4; s++) {
        unsigned m = (s == 0) ? wv.x : (s == 1) ? wv.y : (s == 2) ? wv.z : wv.w;
        int jbase = (lane << 7) + (s << 5);
        while (m) {
            int bit = __ffs(m) - 1;
            m &= m - 1;
            int j = jbase + bit;
            const float4* cj = crow + (size_t)j * 4;
            float4 a = __ldg(cj + 0), bb = __ldg(cj + 1);
            float4 cc = __ldg(cj + 2), dd = __ldg(cj + 3);
            m0.x = fmaxf(m0.x, a.x);  m0.y = fmaxf(m0.y, a.y);
            m0.z = fmaxf(m0.z, a.z);  m0.w = fmaxf(m0.w, a.w);
            m1.x = fmaxf(m1.x, bb.x); m1.y = fmaxf(m1.y, bb.y);
            m1.z = fmaxf(m1.z, bb.z); m1.w = fmaxf(m1.w, bb.w);
            m2.x = fmaxf(m2.x, cc.x); m2.y = fmaxf(m2.y, cc.y);
            m2.z = fmaxf(m2.z, cc.z); m2.w = fmaxf(m2.w, cc.w);
            m3.x = fmaxf(m3.x, dd.x); m3.y = fmaxf(m3.y, dd.y);
            m3.z = fmaxf(m3.z, dd.z); m3.w = fmaxf(m3.w, dd.w);
        }
    }
#define WRED(f) { for (int o = 16; o > 0; o >>= 1) f = fmaxf(f, __shfl_xor_sync(0xffffffffu, f, o)); }
    WRED(m0.x) WRED(m0.y) WRED(m0.z) WRED(m0.w)
    WRED(m1.x) WRED(m1.y) WRED(m1.z) WRED(m1.w)
    WRED(m2.x) WRED(m2.y) WRED(m2.z) WRED(m2.w)
    WRED(m3.x) WRED(m3.y) WRED(m3.z) WRED(m3.w)
#undef WRED
    if (lane == 0) {
        float4* dst = (float4*)&g_adjcon[b][i][0];
        dst[0] = m0; dst[1] = m1; dst[2] = m2; dst[3] = m3;
    }
}

// ---------------------------------------------------------------------------
// K3: per-(image, class) NMS. One block per (b, c).
// ---------------------------------------------------------------------------
__global__ __launch_bounds__(256) void k_nms(
    const float* __restrict__ pro, const float* __restrict__ con,
    const float* __restrict__ boxes, const float* __restrict__ scales,
    const float* __restrict__ conf, float* __restrict__ out, int maskMode)
{
    __shared__ unsigned long long skey[4096];   // 32 KB
    __shared__ int ssorted[NN];                 // 14.4 KB
    __shared__ unsigned int svalid[NW];         // 512 B
    __shared__ int scount;
    __shared__ int sS;

    int c = blockIdx.x, b = blockIdx.y;
    int tid = threadIdx.x;
    int lane = tid & 31;

    if (tid < NW) svalid[tid] = 0u;
    if (tid == 0) { scount = 0; sS = 0; }
    __syncthreads();

    // -------- candidate build: valid0 = pro>=conf && pro>=con && pro>=adj_con
    float confc = conf[c];
    for (int i = tid; i < NN; i += blockDim.x) {
        size_t base = ((size_t)b * NN + i) * NC + c;
        float p  = pro[base];
        float cn = con[base];
        float ac = g_adjcon[b][i][c];
        if (p >= confc && p >= cn && p >= ac) {
            atomicOr(&svalid[i >> 5], 1u << (i & 31));
            int pos = atomicAdd(&scount, 1);
            skey[pos] = ((unsigned long long)__float_as_uint(p) << 32)
                      | (unsigned long long)(0xFFFFFFFFu - (unsigned)i);
        }
    }
    __syncthreads();
    int K = scount;
    int Kp = 1;
    while (Kp < K) Kp <<= 1;

    for (int t = K + tid; t < Kp; t += blockDim.x) skey[t] = 0ULL;
    __syncthreads();

    // -------- bitonic sort descending (score desc, idx asc — matches stable argsort)
    for (int k2 = 2; k2 <= Kp; k2 <<= 1) {
        for (int j = k2 >> 1; j > 0; j >>= 1) {
            for (int i = tid; i < Kp; i += blockDim.x) {
                int ixj = i ^ j;
                if (ixj > i) {
                    unsigned long long a = skey[i], bb2 = skey[ixj];
                    bool up = ((i & k2) == 0);
                    if (up ? (a < bb2) : (a > bb2)) { skey[i] = bb2; skey[ixj] = a; }
                }
            }
            __syncthreads();
        }
    }

    // -------- greedy suppression + survivor extraction (warp 0)
    if (tid < 32) {
        const uint4* adjB = (const uint4*)&g_adj[b][0][0];  // row i -> adjB + i*32
        uint4 v = ((uint4*)svalid)[lane];
        uint4 z = make_uint4(0u, 0u, 0u, 0u);
        uint4 pf0 = z, pf1 = z, pf2 = z, pf3 = z;
#define IDXAT(k) ((int)(0xFFFFFFFFu - (unsigned)skey[(k)]))
        if (K > 0) pf0 = adjB[(size_t)IDXAT(0) * 32 + lane];
        if (K > 1) pf1 = adjB[(size_t)IDXAT(1) * 32 + lane];
        if (K > 2) pf2 = adjB[(size_t)IDXAT(2) * 32 + lane];
        if (K > 3) pf3 = adjB[(size_t)IDXAT(3) * 32 + lane];
#define GSTEP(kk, pf)                                                         \
        if ((kk) < K) {                                                       \
            int idx = IDXAT(kk);                                              \
            int wdq = idx >> 5;                                               \
            unsigned vw;                                                      \
            switch (wdq & 3) {                                                \
                case 0:  vw = __shfl_sync(0xffffffffu, v.x, wdq >> 2); break; \
                case 1:  vw = __shfl_sync(0xffffffffu, v.y, wdq >> 2); break; \
                case 2:  vw = __shfl_sync(0xffffffffu, v.z, wdq >> 2); break; \
                default: vw = __shfl_sync(0xffffffffu, v.w, wdq >> 2); break; \
            }                                                                 \
            if ((vw >> (idx & 31)) & 1u) {                                    \
                v.x &= ~pf.x; v.y &= ~pf.y; v.z &= ~pf.z; v.w &= ~pf.w;       \
            }                                                                 \
            if ((kk) + 4 < K) pf = adjB[(size_t)IDXAT((kk) + 4) * 32 + lane]; \
        }
        for (int k = 0; k < K; k += 4) {
            GSTEP(k,     pf0)
            GSTEP(k + 1, pf1)
            GSTEP(k + 2, pf2)
            GSTEP(k + 3, pf3)
        }
#undef GSTEP
        ((uint4*)svalid)[lane] = v;
        __syncwarp();

        int base = 0;
        for (int k0 = 0; k0 < K; k0 += 32) {
            int kk = k0 + lane;
            bool sv = false;
            int idx = 0;
            if (kk < K) {
                idx = IDXAT(kk);
                sv = (svalid[idx >> 5] >> (idx & 31)) & 1u;
            }
            unsigned mm = __ballot_sync(0xffffffffu, sv);
            if (sv) ssorted[base + __popc(mm & ((1u << lane) - 1u))] = idx;
            base += __popc(mm);
        }
        if (lane == 0) sS = base;
#undef IDXAT
    }
    __syncthreads();

    // -------- write outputs: survivors in slots [0,S), zeros after
    int S = sS;
    float scl = scales[b];
    float* ob = out + ((size_t)(b * NC + c)) * NN * 5;
    for (int t = tid; t < NN; t += blockDim.x) {
        float r0 = 0.f, r1 = 0.f, r2 = 0.f, r3 = 0.f, r4 = 0.f;
        if (t < S) {
            int idx = ssorted[t];
            float4 bxv = __ldg(&((const float4*)boxes)[(size_t)b * NN + idx]);
            float bcx = __fmul_rn(bxv.x, scl);
            float bcy = __fmul_rn(bxv.y, scl);
            float hw = __fmul_rn(0.5f, __fmul_rn(bxv.z, scl));
            float hh = __fmul_rn(0.5f, __fmul_rn(bxv.w, scl));
            r0 = __fsub_rn(bcx, hw);
            r1 = __fsub_rn(bcy, hh);
            r2 = __fadd_rn(bcx, hw);
            r3 = __fadd_rn(bcy, hh);
            r4 = pro[((size_t)b * NN + idx) * NC + c];
        }
        float* p5 = ob + (size_t)t * 5;
        p5[0] = r0; p5[1] = r1; p5[2] = r2; p5[3] = r3; p5[4] = r4;
    }
    if (maskMode == 1) {
        float* mb = out + (size_t)NB * NC * NN * 5 + (size_t)(b * NC + c) * NN;
        for (int t = tid; t < NN; t += blockDim.x) mb[t] = (t < S) ? 1.0f : 0.0f;
    } else if (maskMode == 2) {
        unsigned char* mb = (unsigned char*)(out + (size_t)NB * NC * NN * 5)
                          + (size_t)(b * NC + c) * NN;
        for (int t = tid; t < NN; t += blockDim.x) mb[t] = (t < S) ? 1 : 0;
    }
}

// ---------------------------------------------------------------------------
// Launch
// ---------------------------------------------------------------------------
extern "C" void kernel_launch(void* const* d_in, const int* in_sizes, int n_in,
                              void* d_out, int out_size) {
    const float* pro    = (const float*)d_in[0];  // (B,N,C)
    const float* con    = (const float*)d_in[1];  // (B,N,C)
    const float* boxes  = (const float*)d_in[2];  // (B,N,4)
    const float* scales = (const float*)d_in[3];  // (B,)
    const float* conf   = (const float*)d_in[4];  // (C,)
    float* out = (float*)d_out;

    cudaFuncSetAttribute(k_adj, cudaFuncAttributeMaxDynamicSharedMemorySize, K1_SMEM);

    long long T5 = (long long)NB * NC * NN * 5;   // 1,152,000
    long long TM = (long long)NB * NC * NN;       //   230,400
    int maskMode = 0;
    if ((long long)out_size >= T5 + TM) maskMode = 1;       // mask as float
    else if ((long long)out_size > T5)  maskMode = 2;       // mask as bytes

    k_adj<<<dim3(NN / TRR, NB), 320, K1_SMEM>>>(boxes);
    k_adjcon<<<(NB * NN * 32 + 255) / 256, 256>>>(con);
    k_nms<<<dim3(NC, NB), 256>>>(pro, con, boxes, scales, conf, out, maskMode);
}

// round 4
// speedup vs baseline: 3.0322x; 1.3416x over previous
#include <cuda_runtime.h>
#include <cuda_bf16.h>
#include <stdint.h>

#define NB 4
#define NN 3600
#define NC 16
#define NW 128          /* padded adjacency words per row (113 used) */
#define NWU 113         /* ceil(3600/32) */
#define NPAD 3616       /* boxes padded: 113 tiles * 32 */
#define NT 113          /* 32-wide tiles per dimension */
#define NTRI 6441       /* NT*(NT+1)/2 upper-tri tiles */
#define K1_SMEM (NPAD * 16)

// ---------------------------------------------------------------------------
// Scratch (device globals; no allocation)
// ---------------------------------------------------------------------------
__device__ unsigned int g_adj[NB][NN][NW];     // adjacency bitmask (7.4 MB)
__device__ unsigned int g_val[NB][NC][NW];     // valid0 bitmask per (b,c)

// ---------------------------------------------------------------------------
// K0: zero output, g_val, and adjacency pad words (wide grid, every replay)
// ---------------------------------------------------------------------------
__global__ void k_zero(float* __restrict__ out, int n) {
    int tid = blockIdx.x * blockDim.x + threadIdx.x;
    int stride = gridDim.x * blockDim.x;
    int n4 = n >> 2;
    float4 z4 = make_float4(0.f, 0.f, 0.f, 0.f);
    for (int i = tid; i < n4; i += stride) ((float4*)out)[i] = z4;
    for (int i = (n4 << 2) + tid; i < n; i += stride) out[i] = 0.f;
    unsigned* gv = &g_val[0][0][0];
    for (int i = tid; i < NB * NC * NW; i += stride) gv[i] = 0u;
    unsigned* ga = &g_adj[0][0][0];
    for (int i = tid; i < NB * NN * (NW - NWU); i += stride) {
        int r = i / (NW - NWU), w = i - r * (NW - NWU);
        ga[(size_t)r * NW + NWU + w] = 0u;
    }
}

// ---------------------------------------------------------------------------
// K1: IoU adjacency, symmetric 32x32 tiles (upper triangle only, 2x work cut).
// Each lane owns one column of the tile and serially builds its 32-bit word
// over broadcast rows — no votes, no branches in the hot body. The mirror
// tile is produced by a 5-stage shfl bit-transpose. Boundary-band / 0/0
// cases fall back (rarely, once per tile) to exact __fdiv_rn — bit-identical.
// ---------------------------------------------------------------------------
__global__ __launch_bounds__(320, 3) void k_adj(const float* __restrict__ boxes) {
    int b = blockIdx.y;
    extern __shared__ float4 sb[];   // NPAD boxes as (x1, y1, x2, y2)

    const float4* bx = (const float4*)(boxes + (size_t)b * NN * 4);
    for (int i = threadIdx.x; i < NPAD; i += 320) {
        float4 r;
        if (i < NN) {
            float4 v = bx[i];
            float x1 = __fsub_rn(v.x, __fmul_rn(v.z, 0.5f));
            float y1 = __fsub_rn(v.y, __fmul_rn(v.w, 0.5f));
            r = make_float4(x1, y1, __fadd_rn(x1, v.z), __fadd_rn(y1, v.w));
        } else {
            // pad: inter = 0, area = +inf -> never adjacent, never ambiguous
            r = make_float4(3e30f, 3e30f, -3e30f, -3e30f);
        }
        sb[i] = r;
    }
    __syncthreads();

    int warp = threadIdx.x >> 5, lane = threadIdx.x & 31;
    int nwrp = gridDim.x * 10;

    for (int t = blockIdx.x * 10 + warp; t < NTRI; t += nwrp) {
        // linear -> (ti <= tj) pair, bijective
        int u = t % NT, v = t / NT;
        int ti, tj;
        if (v <= u) { ti = v; tj = u; }
        else        { ti = NT - v; tj = NT - 1 - u; }
        int ib = ti << 5, jb = tj << 5;

        // this lane's column box (tj side)
        float4 vc = sb[jb + lane];
        float ac = __fmul_rn(__fsub_rn(vc.z, vc.x), __fsub_rn(vc.w, vc.y));

        unsigned tw = 0u;
        bool ambAny = false;
#pragma unroll
        for (int r = 0; r < 32; r++) {
            float4 vr = sb[ib + r];  // broadcast row box (ti side)
            float ar = __fmul_rn(__fsub_rn(vr.z, vr.x), __fsub_rn(vr.w, vr.y));
            float ltx = fmaxf(vr.x, vc.x);
            float lty = fmaxf(vr.y, vc.y);
            float rbx = fminf(vr.z, vc.z);
            float rby = fminf(vr.w, vc.w);
            float iw = fmaxf(__fsub_rn(rbx, ltx), 0.0f);
            float ih = fmaxf(__fsub_rn(rby, lty), 0.0f);
            float inter = __fmul_rn(iw, ih);
            float den = __fsub_rn(__fadd_rn(ar, ac), inter);
            bool ok = inter > __fmul_rn(den, 0.4000002f);   // rigorous: iou >= 0.4
            bool df = inter < __fmul_rn(den, 0.3999998f);   // rigorous: iou <  0.4
            ambAny |= (!ok && !df);
            if (ok) tw |= (1u << r);
        }
        if (__any_sync(0xffffffffu, ambAny)) {
            // rare exact redo of the whole tile (bit-identical to reference)
            tw = 0u;
#pragma unroll 1
            for (int r = 0; r < 32; r++) {
                float4 vr = sb[ib + r];
                float ar = __fmul_rn(__fsub_rn(vr.z, vr.x), __fsub_rn(vr.w, vr.y));
                float ltx = fmaxf(vr.x, vc.x);
                float lty = fmaxf(vr.y, vc.y);
                float rbx = fminf(vr.z, vc.z);
                float rby = fminf(vr.w, vc.w);
                float iw = fmaxf(__fsub_rn(rbx, ltx), 0.0f);
                float ih = fmaxf(__fsub_rn(rby, lty), 0.0f);
                float inter = __fmul_rn(iw, ih);
                float den = __fsub_rn(__fadd_rn(ar, ac), inter);
                if (__fdiv_rn(inter, den) >= 0.4f) tw |= (1u << r);
            }
        }

        // tw on lane c: bit r = adj[ib+r][jb+c]  ==  row (jb+c)'s word at ti
        if (ti == tj) {
            tw &= ~(1u << lane);                 // remove eye
            int row = jb + lane;
            if (row < NN) g_adj[b][row][ti] = tw;
        } else {
            int row = jb + lane;
            if (row < NN) g_adj[b][row][ti] = tw;
            // 32x32 bit transpose across lanes -> mirror tile words
            unsigned x = tw;
#pragma unroll
            for (int s = 16; s > 0; s >>= 1) {
                unsigned mask = (s == 16) ? 0x0000FFFFu : (s == 8) ? 0x00FF00FFu
                              : (s == 4) ? 0x0F0F0F0Fu : (s == 2) ? 0x33333333u
                              : 0x55555555u;
                unsigned y = __shfl_xor_sync(0xffffffffu, x, s);
                x = (lane & s) ? ((x & ~mask) | ((y >> s) & mask))
                               : ((x & mask) | ((y & mask) << s));
            }
            int row2 = ib + lane;
            if (row2 < NN) g_adj[b][row2][tj] = x;
        }
    }
}

// ---------------------------------------------------------------------------
// K2: per-box neighbor max of con (all 16 classes) + valid0 bit production.
// One warp per (b, i). valid0 = pro>=conf && pro>=con && pro>=adj_con.
// ---------------------------------------------------------------------------
__global__ __launch_bounds__(256) void k_valid(
    const float* __restrict__ pro, const float* __restrict__ con,
    const float* __restrict__ conf)
{
    int g = (blockIdx.x * blockDim.x + threadIdx.x) >> 5;
    int lane = threadIdx.x & 31;
    if (g >= NB * NN) return;
    int b = g / NN;
    int i = g - b * NN;

    float4 m0 = make_float4(0.f, 0.f, 0.f, 0.f);
    float4 m1 = m0, m2 = m0, m3 = m0;
    const float4* crow = (const float4*)(con + (size_t)b * NN * NC);
    uint4 wv = ((const uint4*)&g_adj[b][i][0])[lane];   // words 4*lane..4*lane+3

#pragma unroll
    for (int s = 0; s < 4; s++) {
        unsigned m = (s == 0) ? wv.x : (s == 1) ? wv.y : (s == 2) ? wv.z : wv.w;
        int jbase = (lane << 7) + (s << 5);
        while (m) {
            int bit = __ffs(m) - 1;
            m &= m - 1;
            int j = jbase + bit;
            const float4* cj = crow + (size_t)j * 4;
            float4 a = __ldg(cj + 0), bb = __ldg(cj + 1);
            float4 cc = __ldg(cj + 2), dd = __ldg(cj + 3);
            m0.x = fmaxf(m0.x, a.x);  m0.y = fmaxf(m0.y, a.y);
            m0.z = fmaxf(m0.z, a.z);  m0.w = fmaxf(m0.w, a.w);
            m1.x = fmaxf(m1.x, bb.x); m1.y = fmaxf(m1.y, bb.y);
            m1.z = fmaxf(m1.z, bb.z); m1.w = fmaxf(m1.w, bb.w);
            m2.x = fmaxf(m2.x, cc.x); m2.y = fmaxf(m2.y, cc.y);
            m2.z = fmaxf(m2.z, cc.z); m2.w = fmaxf(m2.w, cc.w);
            m3.x = fmaxf(m3.x, dd.x); m3.y = fmaxf(m3.y, dd.y);
            m3.z = fmaxf(m3.z, dd.z); m3.w = fmaxf(m3.w, dd.w);
        }
    }
#define WRED(f) { for (int o = 16; o > 0; o >>= 1) f = fmaxf(f, __shfl_xor_sync(0xffffffffu, f, o)); }
    WRED(m0.x) WRED(m0.y) WRED(m0.z) WRED(m0.w)
    WRED(m1.x) WRED(m1.y) WRED(m1.z) WRED(m1.w)
    WRED(m2.x) WRED(m2.y) WRED(m2.z) WRED(m2.w)
    WRED(m3.x) WRED(m3.y) WRED(m3.z) WRED(m3.w)
#undef WRED

    // lanes 0..15: one class each -> candidate bit
    int c = lane;
    if (c < NC) {
        float4 g1 = (c & 8) ? ((c & 4) ? m3 : m2) : ((c & 4) ? m1 : m0);
        float pa = (c & 2) ? g1.z : g1.x;
        float pb = (c & 2) ? g1.w : g1.y;
        float ac = (c & 1) ? pb : pa;
        size_t base = ((size_t)b * NN + i) * NC + c;
        float pv = pro[base];
        float cv = con[base];
        if (pv >= conf[c] && pv >= cv && pv >= ac)
            atomicOr(&g_val[b][c][i >> 5], 1u << (i & 31));
    }
}

// ---------------------------------------------------------------------------
// K3: per-(image, class) NMS. One block per (b, c). Output pre-zeroed by K0.
// ---------------------------------------------------------------------------
__global__ __launch_bounds__(256) void k_nms(
    const float* __restrict__ pro, const float* __restrict__ boxes,
    const float* __restrict__ scales, float* __restrict__ out, int maskMode)
{
    __shared__ unsigned long long skey[4096];   // 32 KB
    __shared__ int ssorted[NN];                 // 14.4 KB
    __shared__ unsigned int svalid[NW];         // 512 B
    __shared__ int scount;
    __shared__ int sS;

    int c = blockIdx.x, b = blockIdx.y;
    int tid = threadIdx.x;
    int lane = tid & 31;

    if (tid == 0) { scount = 0; sS = 0; }
    if (tid < NW) svalid[tid] = g_val[b][c][tid];   // pad words are zero
    __syncthreads();

    // -------- candidate gather from valid0 bitmask
    if (tid < NWU) {
        unsigned w = svalid[tid];
        if (w) {
            int pos = atomicAdd(&scount, __popc(w));
            while (w) {
                int bit = __ffs(w) - 1;
                w &= w - 1;
                int idx = (tid << 5) + bit;
                float p = pro[((size_t)b * NN + idx) * NC + c];
                skey[pos++] = ((unsigned long long)__float_as_uint(p) << 32)
                            | (unsigned long long)(0xFFFFFFFFu - (unsigned)idx);
            }
        }
    }
    __syncthreads();
    int K = scount;
    int Kp = 1;
    while (Kp < K) Kp <<= 1;

    for (int t = K + tid; t < Kp; t += blockDim.x) skey[t] = 0ULL;
    __syncthreads();

    // -------- bitonic sort descending (score desc, idx asc — stable argsort)
    for (int k2 = 2; k2 <= Kp; k2 <<= 1) {
        for (int j = k2 >> 1; j > 0; j >>= 1) {
            for (int i = tid; i < Kp; i += blockDim.x) {
                int ixj = i ^ j;
                if (ixj > i) {
                    unsigned long long a = skey[i], bb2 = skey[ixj];
                    bool up = ((i & k2) == 0);
                    if (up ? (a < bb2) : (a > bb2)) { skey[i] = bb2; skey[ixj] = a; }
                }
            }
            __syncthreads();
        }
    }

    // -------- greedy suppression + survivor extraction (warp 0)
    if (tid < 32) {
        const uint4* adjB = (const uint4*)&g_adj[b][0][0];  // row i -> adjB + i*32
        uint4 v = ((uint4*)svalid)[lane];
        uint4 z = make_uint4(0u, 0u, 0u, 0u);
        uint4 pf0 = z, pf1 = z, pf2 = z, pf3 = z;
#define IDXAT(k) ((int)(0xFFFFFFFFu - (unsigned)skey[(k)]))
        if (K > 0) pf0 = adjB[(size_t)IDXAT(0) * 32 + lane];
        if (K > 1) pf1 = adjB[(size_t)IDXAT(1) * 32 + lane];
        if (K > 2) pf2 = adjB[(size_t)IDXAT(2) * 32 + lane];
        if (K > 3) pf3 = adjB[(size_t)IDXAT(3) * 32 + lane];
#define GSTEP(kk, pf)                                                         \
        if ((kk) < K) {                                                       \
            int idx = IDXAT(kk);                                              \
            int wdq = idx >> 5;                                               \
            unsigned vw;                                                      \
            switch (wdq & 3) {                                                \
                case 0:  vw = __shfl_sync(0xffffffffu, v.x, wdq >> 2); break; \
                case 1:  vw = __shfl_sync(0xffffffffu, v.y, wdq >> 2); break; \
                case 2:  vw = __shfl_sync(0xffffffffu, v.z, wdq >> 2); break; \
                default: vw = __shfl_sync(0xffffffffu, v.w, wdq >> 2); break; \
            }                                                                 \
            if ((vw >> (idx & 31)) & 1u) {                                    \
                v.x &= ~pf.x; v.y &= ~pf.y; v.z &= ~pf.z; v.w &= ~pf.w;       \
            }                                                                 \
            if ((kk) + 4 < K) pf = adjB[(size_t)IDXAT((kk) + 4) * 32 + lane]; \
        }
        for (int k = 0; k < K; k += 4) {
            GSTEP(k,     pf0)
            GSTEP(k + 1, pf1)
            GSTEP(k + 2, pf2)
            GSTEP(k + 3, pf3)
        }
#undef GSTEP
        ((uint4*)svalid)[lane] = v;
        __syncwarp();

        int base = 0;
        for (int k0 = 0; k0 < K; k0 += 32) {
            int kk = k0 + lane;
            bool sv = false;
            int idx = 0;
            if (kk < K) {
                idx = IDXAT(kk);
                sv = (svalid[idx >> 5] >> (idx & 31)) & 1u;
            }
            unsigned mm = __ballot_sync(0xffffffffu, sv);
            if (sv) ssorted[base + __popc(mm & ((1u << lane) - 1u))] = idx;
            base += __popc(mm);
        }
        if (lane == 0) sS = base;
#undef IDXAT
    }
    __syncthreads();

    // -------- write survivor slots only (rest already zero from k_zero)
    int S = sS;
    float scl = scales[b];
    float* ob = out + ((size_t)(b * NC + c)) * NN * 5;
    for (int t = tid; t < S; t += blockDim.x) {
        int idx = ssorted[t];
        float4 bxv = __ldg(&((const float4*)boxes)[(size_t)b * NN + idx]);
        float bcx = __fmul_rn(bxv.x, scl);
        float bcy = __fmul_rn(bxv.y, scl);
        float hw = __fmul_rn(0.5f, __fmul_rn(bxv.z, scl));
        float hh = __fmul_rn(0.5f, __fmul_rn(bxv.w, scl));
        float* p5 = ob + (size_t)t * 5;
        p5[0] = __fsub_rn(bcx, hw);
        p5[1] = __fsub_rn(bcy, hh);
        p5[2] = __fadd_rn(bcx, hw);
        p5[3] = __fadd_rn(bcy, hh);
        p5[4] = pro[((size_t)b * NN + idx) * NC + c];
    }
    if (maskMode == 1) {
        float* mb = out + (size_t)NB * NC * NN * 5 + (size_t)(b * NC + c) * NN;
        for (int t = tid; t < S; t += blockDim.x) mb[t] = 1.0f;
    } else if (maskMode == 2) {
        unsigned char* mb = (unsigned char*)(out + (size_t)NB * NC * NN * 5)
                          + (size_t)(b * NC + c) * NN;
        for (int t = tid; t < S; t += blockDim.x) mb[t] = 1;
    }
}

// ---------------------------------------------------------------------------
// Launch
// ---------------------------------------------------------------------------
extern "C" void kernel_launch(void* const* d_in, const int* in_sizes, int n_in,
                              void* d_out, int out_size) {
    const float* pro    = (const float*)d_in[0];  // (B,N,C)
    const float* con    = (const float*)d_in[1];  // (B,N,C)
    const float* boxes  = (const float*)d_in[2];  // (B,N,4)
    const float* scales = (const float*)d_in[3];  // (B,)
    const float* conf   = (const float*)d_in[4];  // (C,)
    float* out = (float*)d_out;

    cudaFuncSetAttribute(k_adj, cudaFuncAttributeMaxDynamicSharedMemorySize, K1_SMEM);

    long long T5 = (long long)NB * NC * NN * 5;   // 1,152,000
    long long TM = (long long)NB * NC * NN;       //   230,400
    int maskMode = 0;
    if ((long long)out_size >= T5 + TM) maskMode = 1;       // mask as float
    else if ((long long)out_size > T5)  maskMode = 2;       // mask as bytes

    k_zero<<<1024, 256>>>(out, out_size);
    k_adj<<<dim3(111, NB), 320, K1_SMEM>>>(boxes);
    k_valid<<<(NB * NN * 32 + 255) / 256, 256>>>(pro, con, conf);
    k_nms<<<dim3(NC, NB), 256>>>(pro, boxes, scales, out, maskMode);
}

// round 5
// speedup vs baseline: 3.8107x; 1.2567x over previous
#include <cuda_runtime.h>
#include <cuda_bf16.h>
#include <stdint.h>

#define NB 4
#define NN 3600
#define NC 16
#define NW 128          /* padded adjacency words per row (113 used) */
#define NWU 113         /* ceil(3600/32) */
#define NPAD 3616       /* boxes padded: 113 tiles * 32 */
#define NT 113          /* 32-wide tiles per dimension */
#define NTRI 6441       /* NT*(NT+1)/2 upper-tri tiles */
#define K1_SMEM (NPAD * 16)

// ---------------------------------------------------------------------------
// Scratch (device globals; no allocation)
// ---------------------------------------------------------------------------
__device__ unsigned int g_adj[NB][NN][NW];     // adjacency bitmask (7.4 MB)
__device__ unsigned int g_val[NB][NC][NW];     // valid0 bitmask per (b,c)

// ---------------------------------------------------------------------------
// K0: zero output, g_val, and adjacency pad words (wide grid, every replay)
// ---------------------------------------------------------------------------
__global__ void k_zero(float* __restrict__ out, int n) {
    int tid = blockIdx.x * blockDim.x + threadIdx.x;
    int stride = gridDim.x * blockDim.x;
    int n4 = n >> 2;
    float4 z4 = make_float4(0.f, 0.f, 0.f, 0.f);
    for (int i = tid; i < n4; i += stride) ((float4*)out)[i] = z4;
    for (int i = (n4 << 2) + tid; i < n; i += stride) out[i] = 0.f;
    unsigned* gv = &g_val[0][0][0];
    for (int i = tid; i < NB * NC * NW; i += stride) gv[i] = 0u;
    unsigned* ga = &g_adj[0][0][0];
    for (int i = tid; i < NB * NN * (NW - NWU); i += stride) {
        int r = i / (NW - NWU), w = i - r * (NW - NWU);
        ga[(size_t)r * NW + NWU + w] = 0u;
    }
}

// ---------------------------------------------------------------------------
// K1: IoU adjacency, symmetric 32x32 tiles (upper triangle only).
// ---------------------------------------------------------------------------
__global__ __launch_bounds__(320, 3) void k_adj(const float* __restrict__ boxes) {
    int b = blockIdx.y;
    extern __shared__ float4 sb[];   // NPAD boxes as (x1, y1, x2, y2)

    const float4* bx = (const float4*)(boxes + (size_t)b * NN * 4);
    for (int i = threadIdx.x; i < NPAD; i += 320) {
        float4 r;
        if (i < NN) {
            float4 v = bx[i];
            float x1 = __fsub_rn(v.x, __fmul_rn(v.z, 0.5f));
            float y1 = __fsub_rn(v.y, __fmul_rn(v.w, 0.5f));
            r = make_float4(x1, y1, __fadd_rn(x1, v.z), __fadd_rn(y1, v.w));
        } else {
            r = make_float4(3e30f, 3e30f, -3e30f, -3e30f);
        }
        sb[i] = r;
    }
    __syncthreads();

    int warp = threadIdx.x >> 5, lane = threadIdx.x & 31;
    int nwrp = gridDim.x * 10;

    for (int t = blockIdx.x * 10 + warp; t < NTRI; t += nwrp) {
        int u = t % NT, v = t / NT;
        int ti, tj;
        if (v <= u) { ti = v; tj = u; }
        else        { ti = NT - v; tj = NT - 1 - u; }
        int ib = ti << 5, jb = tj << 5;

        float4 vc = sb[jb + lane];
        float ac = __fmul_rn(__fsub_rn(vc.z, vc.x), __fsub_rn(vc.w, vc.y));

        unsigned tw = 0u;
        bool ambAny = false;
#pragma unroll
        for (int r = 0; r < 32; r++) {
            float4 vr = sb[ib + r];
            float ar = __fmul_rn(__fsub_rn(vr.z, vr.x), __fsub_rn(vr.w, vr.y));
            float ltx = fmaxf(vr.x, vc.x);
            float lty = fmaxf(vr.y, vc.y);
            float rbx = fminf(vr.z, vc.z);
            float rby = fminf(vr.w, vc.w);
            float iw = fmaxf(__fsub_rn(rbx, ltx), 0.0f);
            float ih = fmaxf(__fsub_rn(rby, lty), 0.0f);
            float inter = __fmul_rn(iw, ih);
            float den = __fsub_rn(__fadd_rn(ar, ac), inter);
            bool ok = inter > __fmul_rn(den, 0.4000002f);
            bool df = inter < __fmul_rn(den, 0.3999998f);
            ambAny |= (!ok && !df);
            if (ok) tw |= (1u << r);
        }
        if (__any_sync(0xffffffffu, ambAny)) {
            tw = 0u;
#pragma unroll 1
            for (int r = 0; r < 32; r++) {
                float4 vr = sb[ib + r];
                float ar = __fmul_rn(__fsub_rn(vr.z, vr.x), __fsub_rn(vr.w, vr.y));
                float ltx = fmaxf(vr.x, vc.x);
                float lty = fmaxf(vr.y, vc.y);
                float rbx = fminf(vr.z, vc.z);
                float rby = fminf(vr.w, vc.w);
                float iw = fmaxf(__fsub_rn(rbx, ltx), 0.0f);
                float ih = fmaxf(__fsub_rn(rby, lty), 0.0f);
                float inter = __fmul_rn(iw, ih);
                float den = __fsub_rn(__fadd_rn(ar, ac), inter);
                if (__fdiv_rn(inter, den) >= 0.4f) tw |= (1u << r);
            }
        }

        if (ti == tj) {
            tw &= ~(1u << lane);
            int row = jb + lane;
            if (row < NN) g_adj[b][row][ti] = tw;
        } else {
            int row = jb + lane;
            if (row < NN) g_adj[b][row][ti] = tw;
            unsigned x = tw;
#pragma unroll
            for (int s = 16; s > 0; s >>= 1) {
                unsigned mask = (s == 16) ? 0x0000FFFFu : (s == 8) ? 0x00FF00FFu
                              : (s == 4) ? 0x0F0F0F0Fu : (s == 2) ? 0x33333333u
                              : 0x55555555u;
                unsigned y = __shfl_xor_sync(0xffffffffu, x, s);
                x = (lane & s) ? ((x & ~mask) | ((y >> s) & mask))
                               : ((x & mask) | ((y & mask) << s));
            }
            int row2 = ib + lane;
            if (row2 < NN) g_adj[b][row2][tj] = x;
        }
    }
}

// ---------------------------------------------------------------------------
// K2: per-box neighbor max of con (all 16 classes) + valid0 bit production.
// ---------------------------------------------------------------------------
__global__ __launch_bounds__(256) void k_valid(
    const float* __restrict__ pro, const float* __restrict__ con,
    const float* __restrict__ conf)
{
    int g = (blockIdx.x * blockDim.x + threadIdx.x) >> 5;
    int lane = threadIdx.x & 31;
    if (g >= NB * NN) return;
    int b = g / NN;
    int i = g - b * NN;

    float4 m0 = make_float4(0.f, 0.f, 0.f, 0.f);
    float4 m1 = m0, m2 = m0, m3 = m0;
    const float4* crow = (const float4*)(con + (size_t)b * NN * NC);
    uint4 wv = ((const uint4*)&g_adj[b][i][0])[lane];

#pragma unroll
    for (int s = 0; s < 4; s++) {
        unsigned m = (s == 0) ? wv.x : (s == 1) ? wv.y : (s == 2) ? wv.z : wv.w;
        int jbase = (lane << 7) + (s << 5);
        while (m) {
            int bit = __ffs(m) - 1;
            m &= m - 1;
            int j = jbase + bit;
            const float4* cj = crow + (size_t)j * 4;
            float4 a = __ldg(cj + 0), bb = __ldg(cj + 1);
            float4 cc = __ldg(cj + 2), dd = __ldg(cj + 3);
            m0.x = fmaxf(m0.x, a.x);  m0.y = fmaxf(m0.y, a.y);
            m0.z = fmaxf(m0.z, a.z);  m0.w = fmaxf(m0.w, a.w);
            m1.x = fmaxf(m1.x, bb.x); m1.y = fmaxf(m1.y, bb.y);
            m1.z = fmaxf(m1.z, bb.z); m1.w = fmaxf(m1.w, bb.w);
            m2.x = fmaxf(m2.x, cc.x); m2.y = fmaxf(m2.y, cc.y);
            m2.z = fmaxf(m2.z, cc.z); m2.w = fmaxf(m2.w, cc.w);
            m3.x = fmaxf(m3.x, dd.x); m3.y = fmaxf(m3.y, dd.y);
            m3.z = fmaxf(m3.z, dd.z); m3.w = fmaxf(m3.w, dd.w);
        }
    }
#define WRED(f) { for (int o = 16; o > 0; o >>= 1) f = fmaxf(f, __shfl_xor_sync(0xffffffffu, f, o)); }
    WRED(m0.x) WRED(m0.y) WRED(m0.z) WRED(m0.w)
    WRED(m1.x) WRED(m1.y) WRED(m1.z) WRED(m1.w)
    WRED(m2.x) WRED(m2.y) WRED(m2.z) WRED(m2.w)
    WRED(m3.x) WRED(m3.y) WRED(m3.z) WRED(m3.w)
#undef WRED

    int c = lane;
    if (c < NC) {
        float4 g1 = (c & 8) ? ((c & 4) ? m3 : m2) : ((c & 4) ? m1 : m0);
        float pa = (c & 2) ? g1.z : g1.x;
        float pb = (c & 2) ? g1.w : g1.y;
        float ac = (c & 1) ? pb : pa;
        size_t base = ((size_t)b * NN + i) * NC + c;
        float pv = pro[base];
        float cv = con[base];
        if (pv >= conf[c] && pv >= cv && pv >= ac)
            atomicOr(&g_val[b][c][i >> 5], 1u << (i & 31));
    }
}

// ---------------------------------------------------------------------------
// K3: per-(image, class) NMS. One block per (b, c). Output pre-zeroed by K0.
// Greedy chain runs ONLY over candidates adjacent to at least one other
// candidate (isolated candidates provably survive & never suppress).
// ---------------------------------------------------------------------------
__global__ __launch_bounds__(512) void k_nms(
    const float* __restrict__ pro, const float* __restrict__ boxes,
    const float* __restrict__ scales, float* __restrict__ out, int maskMode)
{
    __shared__ unsigned long long skey[4096];   // 32 KB
    __shared__ int ssorted[NN];                 // compact list, then survivors
    __shared__ unsigned int svalid[NW];         // 512 B
    __shared__ unsigned int sconn[NW];          // connectivity bits per sorted pos
    __shared__ int scount;
    __shared__ int sS;
    __shared__ int sKC;

    int c = blockIdx.x, b = blockIdx.y;
    int tid = threadIdx.x;
    int lane = tid & 31;

    if (tid == 0) { scount = 0; sS = 0; sKC = 0; }
    if (tid < NW) { svalid[tid] = g_val[b][c][tid]; sconn[tid] = 0u; }
    __syncthreads();

    // -------- candidate gather from valid0 bitmask
    if (tid < NWU) {
        unsigned w = svalid[tid];
        if (w) {
            int pos = atomicAdd(&scount, __popc(w));
            while (w) {
                int bit = __ffs(w) - 1;
                w &= w - 1;
                int idx = (tid << 5) + bit;
                float p = pro[((size_t)b * NN + idx) * NC + c];
                skey[pos++] = ((unsigned long long)__float_as_uint(p) << 32)
                            | (unsigned long long)(0xFFFFFFFFu - (unsigned)idx);
            }
        }
    }
    __syncthreads();
    int K = scount;
    int Kp = 1;
    while (Kp < K) Kp <<= 1;

    for (int t = K + tid; t < Kp; t += blockDim.x) skey[t] = 0ULL;
    __syncthreads();

    // -------- bitonic sort descending (score desc, idx asc — stable argsort)
    for (int k2 = 2; k2 <= Kp; k2 <<= 1) {
        for (int j = k2 >> 1; j > 0; j >>= 1) {
            for (int i = tid; i < Kp; i += blockDim.x) {
                int ixj = i ^ j;
                if (ixj > i) {
                    unsigned long long a = skey[i], bb2 = skey[ixj];
                    bool up = ((i & k2) == 0);
                    if (up ? (a < bb2) : (a > bb2)) { skey[i] = bb2; skey[ixj] = a; }
                }
            }
            __syncthreads();
        }
    }

#define IDXAT(k) ((int)(0xFFFFFFFFu - (unsigned)skey[(k)]))
    // -------- connectivity: does this candidate touch any other candidate?
    for (int k = tid; k < K; k += blockDim.x) {
        int idx = IDXAT(k);
        const uint4* arow = (const uint4*)&g_adj[b][idx][0];
        const uint4* vmsk = (const uint4*)svalid;
        bool conn = false;
#pragma unroll 4
        for (int w = 0; w < 29; w++) {          // 116 words; pads are zero
            uint4 a = __ldg(arow + w);
            uint4 m = vmsk[w];
            if ((a.x & m.x) | (a.y & m.y) | (a.z & m.z) | (a.w & m.w)) { conn = true; break; }
        }
        if (conn) atomicOr(&sconn[k >> 5], 1u << (k & 31));
    }
    __syncthreads();

    // -------- warp 0: compact connected list, then greedy suppression
    if (tid < 32) {
        // compact sorted positions of connected candidates into ssorted
        int baseC = 0;
        for (int k0 = 0; k0 < K; k0 += 32) {
            int kk = k0 + lane;
            bool cn = (kk < K) && ((sconn[kk >> 5] >> (kk & 31)) & 1u);
            unsigned mm = __ballot_sync(0xffffffffu, cn);
            if (cn) ssorted[baseC + __popc(mm & ((1u << lane) - 1u))] = kk;
            baseC += __popc(mm);
        }
        int KC = baseC;
        if (lane == 0) sKC = KC;

        const uint4* adjB = (const uint4*)&g_adj[b][0][0];  // row i -> adjB + i*32
        uint4 v = ((uint4*)svalid)[lane];
        uint4 z = make_uint4(0u, 0u, 0u, 0u);
        uint4 pf0 = z, pf1 = z, pf2 = z, pf3 = z;
        if (KC > 0) pf0 = adjB[(size_t)IDXAT(ssorted[0]) * 32 + lane];
        if (KC > 1) pf1 = adjB[(size_t)IDXAT(ssorted[1]) * 32 + lane];
        if (KC > 2) pf2 = adjB[(size_t)IDXAT(ssorted[2]) * 32 + lane];
        if (KC > 3) pf3 = adjB[(size_t)IDXAT(ssorted[3]) * 32 + lane];
#define GSTEP(kk, pf)                                                         \
        if ((kk) < KC) {                                                      \
            int idx = IDXAT(ssorted[(kk)]);                                   \
            int wdq = idx >> 5;                                               \
            unsigned vw;                                                      \
            switch (wdq & 3) {                                                \
                case 0:  vw = __shfl_sync(0xffffffffu, v.x, wdq >> 2); break; \
                case 1:  vw = __shfl_sync(0xffffffffu, v.y, wdq >> 2); break; \
                case 2:  vw = __shfl_sync(0xffffffffu, v.z, wdq >> 2); break; \
                default: vw = __shfl_sync(0xffffffffu, v.w, wdq >> 2); break; \
            }                                                                 \
            if ((vw >> (idx & 31)) & 1u) {                                    \
                v.x &= ~pf.x; v.y &= ~pf.y; v.z &= ~pf.z; v.w &= ~pf.w;       \
            }                                                                 \
            if ((kk) + 4 < KC)                                                \
                pf = adjB[(size_t)IDXAT(ssorted[(kk) + 4]) * 32 + lane];      \
        }
        for (int k = 0; k < KC; k += 4) {
            GSTEP(k,     pf0)
            GSTEP(k + 1, pf1)
            GSTEP(k + 2, pf2)
            GSTEP(k + 3, pf3)
        }
#undef GSTEP
        ((uint4*)svalid)[lane] = v;
        __syncwarp();

        // survivor extraction over ALL sorted candidates (final v is exact)
        int base = 0;
        for (int k0 = 0; k0 < K; k0 += 32) {
            int kk = k0 + lane;
            bool sv = false;
            int idx = 0;
            if (kk < K) {
                idx = IDXAT(kk);
                sv = (svalid[idx >> 5] >> (idx & 31)) & 1u;
            }
            unsigned mm = __ballot_sync(0xffffffffu, sv);
            if (sv) ssorted[base + __popc(mm & ((1u << lane) - 1u))] = idx;
            base += __popc(mm);
        }
        if (lane == 0) sS = base;
    }
#undef IDXAT
    __syncthreads();

    // -------- write survivor slots only (rest already zero from k_zero)
    int S = sS;
    float scl = scales[b];
    float* ob = out + ((size_t)(b * NC + c)) * NN * 5;
    for (int t = tid; t < S; t += blockDim.x) {
        int idx = ssorted[t];
        float4 bxv = __ldg(&((const float4*)boxes)[(size_t)b * NN + idx]);
        float bcx = __fmul_rn(bxv.x, scl);
        float bcy = __fmul_rn(bxv.y, scl);
        float hw = __fmul_rn(0.5f, __fmul_rn(bxv.z, scl));
        float hh = __fmul_rn(0.5f, __fmul_rn(bxv.w, scl));
        float* p5 = ob + (size_t)t * 5;
        p5[0] = __fsub_rn(bcx, hw);
        p5[1] = __fsub_rn(bcy, hh);
        p5[2] = __fadd_rn(bcx, hw);
        p5[3] = __fadd_rn(bcy, hh);
        p5[4] = pro[((size_t)b * NN + idx) * NC + c];
    }
    if (maskMode == 1) {
        float* mb = out + (size_t)NB * NC * NN * 5 + (size_t)(b * NC + c) * NN;
        for (int t = tid; t < S; t += blockDim.x) mb[t] = 1.0f;
    } else if (maskMode == 2) {
        unsigned char* mb = (unsigned char*)(out + (size_t)NB * NC * NN * 5)
                          + (size_t)(b * NC + c) * NN;
        for (int t = tid; t < S; t += blockDim.x) mb[t] = 1;
    }
}

// ---------------------------------------------------------------------------
// Launch
// ---------------------------------------------------------------------------
extern "C" void kernel_launch(void* const* d_in, const int* in_sizes, int n_in,
                              void* d_out, int out_size) {
    const float* pro    = (const float*)d_in[0];  // (B,N,C)
    const float* con    = (const float*)d_in[1];  // (B,N,C)
    const float* boxes  = (const float*)d_in[2];  // (B,N,4)
    const float* scales = (const float*)d_in[3];  // (B,)
    const float* conf   = (const float*)d_in[4];  // (C,)
    float* out = (float*)d_out;

    cudaFuncSetAttribute(k_adj, cudaFuncAttributeMaxDynamicSharedMemorySize, K1_SMEM);

    long long T5 = (long long)NB * NC * NN * 5;   // 1,152,000
    long long TM = (long long)NB * NC * NN;       //   230,400
    int maskMode = 0;
    if ((long long)out_size >= T5 + TM) maskMode = 1;       // mask as float
    else if ((long long)out_size > T5)  maskMode = 2;       // mask as bytes

    k_zero<<<1024, 256>>>(out, out_size);
    k_adj<<<dim3(111, NB), 320, K1_SMEM>>>(boxes);
    k_valid<<<(NB * NN * 32 + 255) / 256, 256>>>(pro, con, conf);
    k_nms<<<dim3(NC, NB), 512>>>(pro, boxes, scales, out, maskMode);
}

// round 6
// speedup vs baseline: 3.8192x; 1.0022x over previous
#include <cuda_runtime.h>
#include <cuda_bf16.h>
#include <stdint.h>

#define NB 4
#define NN 3600
#define NC 16
#define NW 128          /* padded adjacency words per row (113 used) */
#define NWU 113         /* ceil(3600/32) */
#define NPAD 3616       /* boxes padded: 113 tiles * 32 */
#define NT 113          /* 32-wide tiles per dimension */
#define NTRI 6441       /* NT*(NT+1)/2 upper-tri tiles */
#define K1_SMEM (NPAD * 16)
#define CMAX 10         /* forward-edge slots per candidate */

/* k_nms dynamic smem layout */
#define SKEY_OFF   0
#define SSORT_OFF  32768
#define SPOS_OFF   47360
#define ALIVE_OFF  54592
#define CNT_OFF    58688
#define TGT_OFF    62784
#define SMEM_NMS   144704

typedef unsigned long long ull;

// ---------------------------------------------------------------------------
// Scratch (device globals; no allocation)
// ---------------------------------------------------------------------------
__device__ unsigned int g_adj[NB][NN][NW];     // adjacency bitmask (7.4 MB)
__device__ unsigned int g_val[NB][NC][NW];     // valid0 bitmask per (b,c)

// ---------------------------------------------------------------------------
// K1: IoU adjacency, symmetric 32x32 tiles (upper triangle only).
// Prologue also zeros: output buffer, g_val, adjacency pad words.
// ---------------------------------------------------------------------------
__global__ __launch_bounds__(320, 3) void k_adj(
    const float* __restrict__ boxes, float* __restrict__ out, int out_n)
{
    int b = blockIdx.y;
    extern __shared__ float4 sb[];   // NPAD boxes as (x1, y1, x2, y2)

    // ---- distributed zeroing (all 444 blocks share the work)
    {
        int gtid = (blockIdx.y * gridDim.x + blockIdx.x) * 320 + threadIdx.x;
        int gstr = gridDim.x * gridDim.y * 320;
        int n4 = out_n >> 2;
        float4 z4 = make_float4(0.f, 0.f, 0.f, 0.f);
        for (int i = gtid; i < n4; i += gstr) ((float4*)out)[i] = z4;
        for (int i = (n4 << 2) + gtid; i < out_n; i += gstr) out[i] = 0.f;
        unsigned* gv = &g_val[0][0][0];
        for (int i = gtid; i < NB * NC * NW; i += gstr) gv[i] = 0u;
        unsigned* ga = &g_adj[0][0][0];
        for (int i = gtid; i < NB * NN * (NW - NWU); i += gstr) {
            int r = i / (NW - NWU), w = i - r * (NW - NWU);
            ga[(size_t)r * NW + NWU + w] = 0u;
        }
    }

    const float4* bx = (const float4*)(boxes + (size_t)b * NN * 4);
    for (int i = threadIdx.x; i < NPAD; i += 320) {
        float4 r;
        if (i < NN) {
            float4 v = bx[i];
            float x1 = __fsub_rn(v.x, __fmul_rn(v.z, 0.5f));
            float y1 = __fsub_rn(v.y, __fmul_rn(v.w, 0.5f));
            r = make_float4(x1, y1, __fadd_rn(x1, v.z), __fadd_rn(y1, v.w));
        } else {
            r = make_float4(3e30f, 3e30f, -3e30f, -3e30f);
        }
        sb[i] = r;
    }
    __syncthreads();

    int warp = threadIdx.x >> 5, lane = threadIdx.x & 31;
    int nwrp = gridDim.x * 10;

    for (int t = blockIdx.x * 10 + warp; t < NTRI; t += nwrp) {
        int u = t % NT, v = t / NT;
        int ti, tj;
        if (v <= u) { ti = v; tj = u; }
        else        { ti = NT - v; tj = NT - 1 - u; }
        int ib = ti << 5, jb = tj << 5;

        float4 vc = sb[jb + lane];
        float ac = __fmul_rn(__fsub_rn(vc.z, vc.x), __fsub_rn(vc.w, vc.y));

        unsigned tw = 0u;
        bool ambAny = false;
#pragma unroll
        for (int r = 0; r < 32; r++) {
            float4 vr = sb[ib + r];
            float ar = __fmul_rn(__fsub_rn(vr.z, vr.x), __fsub_rn(vr.w, vr.y));
            float ltx = fmaxf(vr.x, vc.x);
            float lty = fmaxf(vr.y, vc.y);
            float rbx = fminf(vr.z, vc.z);
            float rby = fminf(vr.w, vc.w);
            float iw = fmaxf(__fsub_rn(rbx, ltx), 0.0f);
            float ih = fmaxf(__fsub_rn(rby, lty), 0.0f);
            float inter = __fmul_rn(iw, ih);
            float den = __fsub_rn(__fadd_rn(ar, ac), inter);
            bool ok = inter > __fmul_rn(den, 0.4000002f);
            bool df = inter < __fmul_rn(den, 0.3999998f);
            ambAny |= (!ok && !df);
            if (ok) tw |= (1u << r);
        }
        if (__any_sync(0xffffffffu, ambAny)) {
            tw = 0u;
#pragma unroll 1
            for (int r = 0; r < 32; r++) {
                float4 vr = sb[ib + r];
                float ar = __fmul_rn(__fsub_rn(vr.z, vr.x), __fsub_rn(vr.w, vr.y));
                float ltx = fmaxf(vr.x, vc.x);
                float lty = fmaxf(vr.y, vc.y);
                float rbx = fminf(vr.z, vc.z);
                float rby = fminf(vr.w, vc.w);
                float iw = fmaxf(__fsub_rn(rbx, ltx), 0.0f);
                float ih = fmaxf(__fsub_rn(rby, lty), 0.0f);
                float inter = __fmul_rn(iw, ih);
                float den = __fsub_rn(__fadd_rn(ar, ac), inter);
                if (__fdiv_rn(inter, den) >= 0.4f) tw |= (1u << r);
            }
        }

        if (ti == tj) {
            tw &= ~(1u << lane);
            int row = jb + lane;
            if (row < NN) g_adj[b][row][ti] = tw;
        } else {
            int row = jb + lane;
            if (row < NN) g_adj[b][row][ti] = tw;
            unsigned x = tw;
#pragma unroll
            for (int s = 16; s > 0; s >>= 1) {
                unsigned mask = (s == 16) ? 0x0000FFFFu : (s == 8) ? 0x00FF00FFu
                              : (s == 4) ? 0x0F0F0F0Fu : (s == 2) ? 0x33333333u
                              : 0x55555555u;
                unsigned y = __shfl_xor_sync(0xffffffffu, x, s);
                x = (lane & s) ? ((x & ~mask) | ((y >> s) & mask))
                               : ((x & mask) | ((y & mask) << s));
            }
            int row2 = ib + lane;
            if (row2 < NN) g_adj[b][row2][tj] = x;
        }
    }
}

// ---------------------------------------------------------------------------
// K2: per-box neighbor max of con (all 16 classes) + valid0 bit production.
// ---------------------------------------------------------------------------
__global__ __launch_bounds__(256) void k_valid(
    const float* __restrict__ pro, const float* __restrict__ con,
    const float* __restrict__ conf)
{
    int g = (blockIdx.x * blockDim.x + threadIdx.x) >> 5;
    int lane = threadIdx.x & 31;
    if (g >= NB * NN) return;
    int b = g / NN;
    int i = g - b * NN;

    float4 m0 = make_float4(0.f, 0.f, 0.f, 0.f);
    float4 m1 = m0, m2 = m0, m3 = m0;
    const float4* crow = (const float4*)(con + (size_t)b * NN * NC);
    uint4 wv = ((const uint4*)&g_adj[b][i][0])[lane];

#pragma unroll
    for (int s = 0; s < 4; s++) {
        unsigned m = (s == 0) ? wv.x : (s == 1) ? wv.y : (s == 2) ? wv.z : wv.w;
        int jbase = (lane << 7) + (s << 5);
        while (m) {
            int bit = __ffs(m) - 1;
            m &= m - 1;
            int j = jbase + bit;
            const float4* cj = crow + (size_t)j * 4;
            float4 a = __ldg(cj + 0), bb = __ldg(cj + 1);
            float4 cc = __ldg(cj + 2), dd = __ldg(cj + 3);
            m0.x = fmaxf(m0.x, a.x);  m0.y = fmaxf(m0.y, a.y);
            m0.z = fmaxf(m0.z, a.z);  m0.w = fmaxf(m0.w, a.w);
            m1.x = fmaxf(m1.x, bb.x); m1.y = fmaxf(m1.y, bb.y);
            m1.z = fmaxf(m1.z, bb.z); m1.w = fmaxf(m1.w, bb.w);
            m2.x = fmaxf(m2.x, cc.x); m2.y = fmaxf(m2.y, cc.y);
            m2.z = fmaxf(m2.z, cc.z); m2.w = fmaxf(m2.w, cc.w);
            m3.x = fmaxf(m3.x, dd.x); m3.y = fmaxf(m3.y, dd.y);
            m3.z = fmaxf(m3.z, dd.z); m3.w = fmaxf(m3.w, dd.w);
        }
    }
#define WRED(f) { for (int o = 16; o > 0; o >>= 1) f = fmaxf(f, __shfl_xor_sync(0xffffffffu, f, o)); }
    WRED(m0.x) WRED(m0.y) WRED(m0.z) WRED(m0.w)
    WRED(m1.x) WRED(m1.y) WRED(m1.z) WRED(m1.w)
    WRED(m2.x) WRED(m2.y) WRED(m2.z) WRED(m2.w)
    WRED(m3.x) WRED(m3.y) WRED(m3.z) WRED(m3.w)
#undef WRED

    int c = lane;
    if (c < NC) {
        float4 g1 = (c & 8) ? ((c & 4) ? m3 : m2) : ((c & 4) ? m1 : m0);
        float pa = (c & 2) ? g1.z : g1.x;
        float pb = (c & 2) ? g1.w : g1.y;
        float ac = (c & 1) ? pb : pa;
        size_t base = ((size_t)b * NN + i) * NC + c;
        float pv = pro[base];
        float cv = con[base];
        if (pv >= conf[c] && pv >= cv && pv >= ac)
            atomicOr(&g_val[b][c][i >> 5], 1u << (i & 31));
    }
}

// ---------------------------------------------------------------------------
// K3: per-(image, class) NMS. One block per (b, c).
// Sparse forward-edge greedy on a byte alive-array (single-thread chain),
// with warp-chain fallback if any candidate exceeds CMAX forward edges.
// ---------------------------------------------------------------------------
__global__ __launch_bounds__(512) void k_nms(
    const float* __restrict__ pro, const float* __restrict__ boxes,
    const float* __restrict__ scales, float* __restrict__ out, int maskMode)
{
    extern __shared__ unsigned char dyn[];
    ull* skey            = (ull*)(dyn + SKEY_OFF);            // [4096]
    int* ssorted         = (int*)(dyn + SSORT_OFF);           // [3648]
    unsigned short* spos = (unsigned short*)(dyn + SPOS_OFF); // [3616]
    unsigned char* alive = dyn + ALIVE_OFF;                   // [4096]
    unsigned char* cnt8  = dyn + CNT_OFF;                     // [4096]
    unsigned short* tgt  = (unsigned short*)(dyn + TGT_OFF);  // [4096*CMAX]

    __shared__ __align__(16) unsigned int svalid[NW];
    __shared__ int scount, sS, sKC, sOVF;

    int c = blockIdx.x, b = blockIdx.y;
    int tid = threadIdx.x;
    int lane = tid & 31;

    if (tid == 0) { scount = 0; sS = 0; sKC = 0; sOVF = 0; }
    if (tid < NW) svalid[tid] = g_val[b][c][tid];   // pad words are zero
    __syncthreads();

    // -------- candidate gather from valid0 bitmask
    if (tid < NWU) {
        unsigned w = svalid[tid];
        if (w) {
            int pos = atomicAdd(&scount, __popc(w));
            while (w) {
                int bit = __ffs(w) - 1;
                w &= w - 1;
                int idx = (tid << 5) + bit;
                float p = pro[((size_t)b * NN + idx) * NC + c];
                skey[pos++] = ((ull)__float_as_uint(p) << 32)
                            | (ull)(0xFFFFFFFFu - (unsigned)idx);
            }
        }
    }
    __syncthreads();
    int K = scount;
    int Kp = 32;
    while (Kp < K) Kp <<= 1;

    for (int t = K + tid; t < Kp; t += 512) skey[t] = 0ULL;
    __syncthreads();

    // -------- hybrid bitonic sort, descending (score desc, idx asc)
    for (int k2 = 2; k2 <= Kp; k2 <<= 1) {
        for (int j = k2 >> 1; j >= 32; j >>= 1) {
            for (int i = tid; i < Kp; i += 512) {
                int ixj = i ^ j;
                if (ixj > i) {
                    ull a = skey[i], bb2 = skey[ixj];
                    bool up = ((i & k2) == 0);
                    if (up ? (a < bb2) : (a > bb2)) { skey[i] = bb2; skey[ixj] = a; }
                }
            }
            __syncthreads();
        }
        // tail: j = min(k2/2,16) .. 1 in registers via shfl (32-segments)
        int jt = (k2 >> 1) < 16 ? (k2 >> 1) : 16;
        for (int i = tid; i < Kp; i += 512) {
            ull x = skey[i];
            bool up = ((i & k2) == 0);
            for (int j = jt; j >= 1; j >>= 1) {
                ull y = __shfl_xor_sync(0xffffffffu, x, j);
                bool keepmax = (((i & j) == 0) == up);
                x = keepmax ? (x > y ? x : y) : (x < y ? x : y);
            }
            skey[i] = x;
        }
        __syncthreads();
    }

#define IDXAT(k) ((int)(0xFFFFFFFFu - (unsigned)skey[(k)]))
    // -------- position map + alive/cnt init
    for (int k = tid; k < K; k += 512) {
        spos[IDXAT(k)] = (unsigned short)k;
        alive[k] = 1;
        cnt8[k] = 0;
    }
    __syncthreads();

    // -------- forward candidate->candidate edge lists (sorted positions)
    for (int k = tid; k < K; k += 512) {
        int idx = IDXAT(k);
        const uint4* arow = (const uint4*)&g_adj[b][idx][0];
        const uint4* vmsk = (const uint4*)svalid;
        int n = 0;
#pragma unroll 4
        for (int w = 0; w < 29; w++) {          // 116 words; pads zero
            uint4 a = __ldg(arow + w);
            uint4 m = vmsk[w];
            unsigned q0 = a.x & m.x, q1 = a.y & m.y, q2 = a.z & m.z, q3 = a.w & m.w;
            if (!(q0 | q1 | q2 | q3)) continue;
            int jb0 = w << 7;
#define PROC(q, off)                                                      \
            while (q) {                                                   \
                int bit = __ffs(q) - 1; q &= q - 1;                       \
                int p = spos[jb0 + (off) + bit];                          \
                if (p > k) { if (n < CMAX) tgt[k * CMAX + n] = (unsigned short)p; n++; } \
            }
            PROC(q0, 0) PROC(q1, 32) PROC(q2, 64) PROC(q3, 96)
#undef PROC
        }
        if (n > CMAX) { cnt8[k] = CMAX; sOVF = 1; }
        else cnt8[k] = (unsigned char)n;
    }
    __syncthreads();

    // -------- warp 0: compact source list; chain; extraction
    if (tid < 32) {
        int baseC = 0;
        for (int k0 = 0; k0 < K; k0 += 32) {
            int kk = k0 + lane;
            bool cn = (kk < K) && (cnt8[kk] > 0);
            unsigned mm = __ballot_sync(0xffffffffu, cn);
            if (cn) ssorted[baseC + __popc(mm & ((1u << lane) - 1u))] = kk;
            baseC += __popc(mm);
        }
        if (lane == 0) sKC = baseC;
        __syncwarp();
        int KSRC = sKC;
        int ovf = sOVF;

        if (!ovf) {
            // ---- single-thread sparse chain over sources, batches of 8
            if (lane == 0) {
                for (int kb = 0; kb < KSRC; kb += 8) {
                    int nb = KSRC - kb; if (nb > 8) nb = 8;
                    int pos[8]; unsigned char al[8];
#pragma unroll
                    for (int r = 0; r < 8; r++)
                        if (r < nb) pos[r] = ssorted[kb + r];
#pragma unroll
                    for (int r = 0; r < 8; r++)
                        if (r < nb) al[r] = alive[pos[r]];
                    for (int r = 0; r < nb; r++) {
                        if (!al[r]) continue;
                        int p = pos[r];
                        int c0 = cnt8[p];
                        for (int e = 0; e < c0; e++) {
                            int tg = tgt[p * CMAX + e];
                            alive[tg] = 0;
                            for (int r2 = r + 1; r2 < nb; r2++)
                                if (pos[r2] == tg) al[r2] = 0;
                        }
                    }
                }
            }
            __syncwarp();
        } else {
            // ---- fallback: proven warp-shfl chain over ALL K candidates
            const uint4* adjB = (const uint4*)&g_adj[b][0][0];
            uint4 v = ((uint4*)svalid)[lane];
            uint4 z = make_uint4(0u, 0u, 0u, 0u);
            uint4 pf0 = z, pf1 = z, pf2 = z, pf3 = z;
            if (K > 0) pf0 = adjB[(size_t)IDXAT(0) * 32 + lane];
            if (K > 1) pf1 = adjB[(size_t)IDXAT(1) * 32 + lane];
            if (K > 2) pf2 = adjB[(size_t)IDXAT(2) * 32 + lane];
            if (K > 3) pf3 = adjB[(size_t)IDXAT(3) * 32 + lane];
#define GSTEP(kk, pf)                                                         \
            if ((kk) < K) {                                                   \
                int idx = IDXAT(kk);                                          \
                int wdq = idx >> 5;                                           \
                unsigned vw;                                                  \
                switch (wdq & 3) {                                            \
                    case 0:  vw = __shfl_sync(0xffffffffu, v.x, wdq >> 2); break; \
                    case 1:  vw = __shfl_sync(0xffffffffu, v.y, wdq >> 2); break; \
                    case 2:  vw = __shfl_sync(0xffffffffu, v.z, wdq >> 2); break; \
                    default: vw = __shfl_sync(0xffffffffu, v.w, wdq >> 2); break; \
                }                                                             \
                if ((vw >> (idx & 31)) & 1u) {                                \
                    v.x &= ~pf.x; v.y &= ~pf.y; v.z &= ~pf.z; v.w &= ~pf.w;   \
                }                                                             \
                if ((kk) + 4 < K) pf = adjB[(size_t)IDXAT((kk) + 4) * 32 + lane]; \
            }
            for (int k = 0; k < K; k += 4) {
                GSTEP(k,     pf0)
                GSTEP(k + 1, pf1)
                GSTEP(k + 2, pf2)
                GSTEP(k + 3, pf3)
            }
#undef GSTEP
            ((uint4*)svalid)[lane] = v;
            __syncwarp();
        }

        // ---- survivor extraction in sorted order
        int base = 0;
        for (int k0 = 0; k0 < K; k0 += 32) {
            int kk = k0 + lane;
            bool sv = false;
            int idx = 0;
            if (kk < K) {
                idx = IDXAT(kk);
                sv = ovf ? (((svalid[idx >> 5] >> (idx & 31)) & 1u) != 0)
                         : (alive[kk] != 0);
            }
            unsigned mm = __ballot_sync(0xffffffffu, sv);
            if (sv) ssorted[base + __popc(mm & ((1u << lane) - 1u))] = idx;
            base += __popc(mm);
        }
        if (lane == 0) sS = base;
    }
#undef IDXAT
    __syncthreads();

    // -------- write survivor slots only (rest already zero via k_adj prologue)
    int S = sS;
    float scl = scales[b];
    float* ob = out + ((size_t)(b * NC + c)) * NN * 5;
    for (int t = tid; t < S; t += 512) {
        int idx = ssorted[t];
        float4 bxv = __ldg(&((const float4*)boxes)[(size_t)b * NN + idx]);
        float bcx = __fmul_rn(bxv.x, scl);
        float bcy = __fmul_rn(bxv.y, scl);
        float hw = __fmul_rn(0.5f, __fmul_rn(bxv.z, scl));
        float hh = __fmul_rn(0.5f, __fmul_rn(bxv.w, scl));
        float* p5 = ob + (size_t)t * 5;
        p5[0] = __fsub_rn(bcx, hw);
        p5[1] = __fsub_rn(bcy, hh);
        p5[2] = __fadd_rn(bcx, hw);
        p5[3] = __fadd_rn(bcy, hh);
        p5[4] = pro[((size_t)b * NN + idx) * NC + c];
    }
    if (maskMode == 1) {
        float* mb = out + (size_t)NB * NC * NN * 5 + (size_t)(b * NC + c) * NN;
        for (int t = tid; t < S; t += 512) mb[t] = 1.0f;
    } else if (maskMode == 2) {
        unsigned char* mb = (unsigned char*)(out + (size_t)NB * NC * NN * 5)
                          + (size_t)(b * NC + c) * NN;
        for (int t = tid; t < S; t += 512) mb[t] = 1;
    }
}

// ---------------------------------------------------------------------------
// Launch
// ---------------------------------------------------------------------------
extern "C" void kernel_launch(void* const* d_in, const int* in_sizes, int n_in,
                              void* d_out, int out_size) {
    const float* pro    = (const float*)d_in[0];  // (B,N,C)
    const float* con    = (const float*)d_in[1];  // (B,N,C)
    const float* boxes  = (const float*)d_in[2];  // (B,N,4)
    const float* scales = (const float*)d_in[3];  // (B,)
    const float* conf   = (const float*)d_in[4];  // (C,)
    float* out = (float*)d_out;

    cudaFuncSetAttribute(k_adj, cudaFuncAttributeMaxDynamicSharedMemorySize, K1_SMEM);
    cudaFuncSetAttribute(k_nms, cudaFuncAttributeMaxDynamicSharedMemorySize, SMEM_NMS);

    long long T5 = (long long)NB * NC * NN * 5;   // 1,152,000
    long long TM = (long long)NB * NC * NN;       //   230,400
    int maskMode = 0;
    if ((long long)out_size >= T5 + TM) maskMode = 1;       // mask as float
    else if ((long long)out_size > T5)  maskMode = 2;       // mask as bytes

    k_adj<<<dim3(111, NB), 320, K1_SMEM>>>(boxes, out, out_size);
    k_valid<<<(NB * NN * 32 + 255) / 256, 256>>>(pro, con, conf);
    k_nms<<<dim3(NC, NB), 512, SMEM_NMS>>>(pro, boxes, scales, out, maskMode);
}